// round 11
// baseline (speedup 1.0000x reference)
#include <cuda_runtime.h>
#include <cuda_fp16.h>
#include <cstdint>
#include <math.h>

#define BATCH  4
#define SEQ    2048
#define DMODEL 1024
#define NHEADS 16
#define DHEAD  64
#define NBH    (BATCH * NHEADS)   // 64
#define MTOT   (BATCH * SEQ)      // 8192

// ---------------- scratch (static device arrays; allocation-free) ----------
// Q,K,V all [bh][s][d] (d contiguous). Q pre-scaled by 0.125*log2(e).
__device__ __half g_Qhi[(size_t)NBH * SEQ * DHEAD];
__device__ __half g_Qlo[(size_t)NBH * SEQ * DHEAD];
__device__ __half g_Khi[(size_t)NBH * SEQ * DHEAD];
__device__ __half g_Klo[(size_t)NBH * SEQ * DHEAD];
__device__ __half g_Vhi[(size_t)NBH * SEQ * DHEAD];
__device__ __half g_Vlo[(size_t)NBH * SEQ * DHEAD];

__device__ __half g_Xhi[(size_t)MTOT * DMODEL];
__device__ __half g_Xlo[(size_t)MTOT * DMODEL];
__device__ __half g_WThi[(size_t)3 * DMODEL * DMODEL];  // [which][n][k]
__device__ __half g_WTlo[(size_t)3 * DMODEL * DMODEL];

// ---------------- helpers ---------------------------------------------------
__device__ __forceinline__ void cp16(uint32_t dst, const void* src) {
    asm volatile("cp.async.cg.shared.global [%0], [%1], 16;" :: "r"(dst), "l"(src));
}
#define CP_COMMIT() asm volatile("cp.async.commit_group;" ::: "memory")
#define CP_WAIT(n)  asm volatile("cp.async.wait_group %0;" :: "n"(n) : "memory")

__device__ __forceinline__ uint32_t smem_u32(const void* p) {
    uint32_t a;
    asm("{ .reg .u64 t; cvta.to.shared.u64 t, %1; cvt.u32.u64 %0, t; }" : "=r"(a) : "l"(p));
    return a;
}
__device__ __forceinline__ void mma16816(float* c, const uint32_t* a, const uint32_t* b) {
    asm volatile("mma.sync.aligned.m16n8k16.row.col.f32.f16.f16.f32 "
                 "{%0,%1,%2,%3}, {%4,%5,%6,%7}, {%8,%9}, {%0,%1,%2,%3};"
                 : "+f"(c[0]), "+f"(c[1]), "+f"(c[2]), "+f"(c[3])
                 : "r"(a[0]), "r"(a[1]), "r"(a[2]), "r"(a[3]), "r"(b[0]), "r"(b[1]));
}
__device__ __forceinline__ void ldsm4(uint32_t* r, uint32_t addr) {
    asm volatile("ldmatrix.sync.aligned.m8n8.x4.shared.b16 {%0,%1,%2,%3}, [%4];"
                 : "=r"(r[0]), "=r"(r[1]), "=r"(r[2]), "=r"(r[3]) : "r"(addr));
}
__device__ __forceinline__ void ldsm4t(uint32_t* r, uint32_t addr) {
    asm volatile("ldmatrix.sync.aligned.m8n8.x4.trans.shared.b16 {%0,%1,%2,%3}, [%4];"
                 : "=r"(r[0]), "=r"(r[1]), "=r"(r[2]), "=r"(r[3]) : "r"(addr));
}
__device__ __forceinline__ uint32_t pack2h(__half a, __half b) {
    __half2 t = __halves2half2(a, b);
    return *(uint32_t*)&t;
}
// MUFU exp2 (logits are pre-scaled to base-2 domain)
__device__ __forceinline__ float fex2(float x) {
    float r;
    asm("ex2.approx.f32 %0, %1;" : "=f"(r) : "f"(x));
    return r;
}

// ---------------- conversion kernels ---------------------------------------
__global__ void split_x_kernel(const float* __restrict__ X)
{
    size_t i = ((size_t)blockIdx.x * blockDim.x + threadIdx.x) * 4;
    float4 v = *(const float4*)(X + i);
    float f[4] = {v.x, v.y, v.z, v.w};
#pragma unroll
    for (int j = 0; j < 4; j++) {
        __half hi = __float2half_rn(f[j]);
        g_Xhi[i + j] = hi;
        g_Xlo[i + j] = __float2half_rn(f[j] - __half2float(hi));
    }
}

__global__ void split_wt_kernel(const float* __restrict__ Wq,
                                const float* __restrict__ Wk,
                                const float* __restrict__ Wv)
{
    __shared__ float t[32][33];
    const float* W = (blockIdx.z == 0) ? Wq : (blockIdx.z == 1) ? Wk : Wv;
    int tx = threadIdx.x, ty = threadIdx.y;
    int n = blockIdx.x * 32 + tx;
#pragma unroll
    for (int i = 0; i < 4; i++) {
        int k = blockIdx.y * 32 + ty + i * 8;
        t[ty + i * 8][tx] = W[(size_t)k * DMODEL + n];
    }
    __syncthreads();
    size_t base = (size_t)blockIdx.z * DMODEL * DMODEL;
#pragma unroll
    for (int i = 0; i < 4; i++) {
        int nn = blockIdx.x * 32 + ty + i * 8;
        int kk = blockIdx.y * 32 + tx;
        float f = t[tx][ty + i * 8];
        __half hi = __float2half_rn(f);
        g_WThi[base + (size_t)nn * DMODEL + kk] = hi;
        g_WTlo[base + (size_t)nn * DMODEL + kk] = __float2half_rn(f - __half2float(hi));
    }
}

// ---------------- mma.sync split-fp16 projection GEMM ----------------------
constexpr int GKC = 32;
constexpr int NCHUNK = DMODEL / GKC;       // 32
constexpr int SST = 40;
constexpr uint32_t AHI = 0;
constexpr uint32_t ALO = 128 * SST * 2;
constexpr uint32_t BHI = 2 * 128 * SST * 2;
constexpr uint32_t BLO = 3 * 128 * SST * 2;
constexpr uint32_t STAGE = 4 * 128 * SST * 2;      // 40960
constexpr uint32_t GEMM_SMEM = 2 * STAGE;          // 81920

__global__ __launch_bounds__(256, 2)
void qkv_mma_kernel()
{
    extern __shared__ uint8_t sm[];
    const uint32_t sb = smem_u32(sm);

    const int tid = threadIdx.x;
    const int lane = tid & 31;
    const int warp = tid >> 5;
    const int wy = warp >> 2;
    const int wx = warp & 3;
    const int gid = lane >> 2;
    const int tig = lane & 3;

    const int which = blockIdx.z;
    const int n0 = blockIdx.x * 128;
    const int m0 = blockIdx.y * 128;

    const __half* __restrict__ WThi = g_WThi + (size_t)which * DMODEL * DMODEL;
    const __half* __restrict__ WTlo = g_WTlo + (size_t)which * DMODEL * DMODEL;

    const uint32_t a_off = ((uint32_t)((lane & 15) * SST) + ((uint32_t)(lane >> 4) << 3)) * 2;
    const uint32_t b_off = ((uint32_t)(((lane & 7) + ((lane >> 4) << 3)) * SST) + (uint32_t)(lane & 8)) * 2;

    auto load_chunk = [&](int c, int s) {
        const uint32_t stage = sb + (uint32_t)s * STAGE;
        const int c0 = c * GKC;
#pragma unroll
        for (int it = 0; it < 2; it++) {
            int idx = tid + it * 256;
            int r = idx >> 2, kg = idx & 3;
            uint32_t doff = (uint32_t)(r * SST * 2 + kg * 16);
            size_t asrc = (size_t)(m0 + r) * DMODEL + c0 + kg * 8;
            size_t bsrc = (size_t)(n0 + r) * DMODEL + c0 + kg * 8;
            cp16(stage + AHI + doff, g_Xhi + asrc);
            cp16(stage + ALO + doff, g_Xlo + asrc);
            cp16(stage + BHI + doff, WThi + bsrc);
            cp16(stage + BLO + doff, WTlo + bsrc);
        }
    };

    float acc[4][4][4];
#pragma unroll
    for (int mt = 0; mt < 4; mt++)
#pragma unroll
        for (int nt = 0; nt < 4; nt++)
#pragma unroll
            for (int j = 0; j < 4; j++) acc[mt][nt][j] = 0.f;

    load_chunk(0, 0);
    CP_COMMIT();

    for (int c = 0; c < NCHUNK; c++) {
        const int s = c & 1;
        if (c + 1 < NCHUNK) {
            load_chunk(c + 1, s ^ 1);
            CP_COMMIT();
            CP_WAIT(1);
        } else {
            CP_WAIT(0);
        }
        __syncthreads();

        const uint32_t stg = sb + (uint32_t)s * STAGE;

#pragma unroll
        for (int ks = 0; ks < 2; ks++) {
            const uint32_t koff = (uint32_t)(ks * 32);
            uint32_t bh4[2][4], bl4[2][4];
#pragma unroll
            for (int np = 0; np < 2; np++) {
                const uint32_t brow = (uint32_t)((wx * 32 + np * 16) * SST * 2);
                ldsm4(bh4[np], stg + BHI + brow + koff + b_off);
                ldsm4(bl4[np], stg + BLO + brow + koff + b_off);
            }
#pragma unroll
            for (int mt = 0; mt < 4; mt++) {
                const uint32_t arow = (uint32_t)((wy * 64 + mt * 16) * SST * 2);
                uint32_t ah[4], al[4];
                ldsm4(ah, stg + AHI + arow + koff + a_off);
                ldsm4(al, stg + ALO + arow + koff + a_off);
#pragma unroll
                for (int np = 0; np < 2; np++) {
                    mma16816(acc[mt][2 * np],     ah, bh4[np]);
                    mma16816(acc[mt][2 * np],     ah, bl4[np]);
                    mma16816(acc[mt][2 * np],     al, bh4[np]);
                    mma16816(acc[mt][2 * np + 1], ah, bh4[np] + 2);
                    mma16816(acc[mt][2 * np + 1], ah, bl4[np] + 2);
                    mma16816(acc[mt][2 * np + 1], al, bh4[np] + 2);
                }
            }
        }
        __syncthreads();
    }

    // ---- epilogue: emit fp16 hi/lo, all [bh][s][d] ------------------------
    const float QSCALE = 0.18033688011112042f;   // 0.125 * log2(e)
#pragma unroll
    for (int mt = 0; mt < 4; mt++) {
#pragma unroll
        for (int hr = 0; hr < 2; hr++) {
            const int m = m0 + wy * 64 + mt * 16 + gid + hr * 8;
            const int bbp = m >> 11;
            const int sIdx = m & 2047;
#pragma unroll
            for (int nt = 0; nt < 4; nt++) {
                const int n = n0 + wx * 32 + nt * 8 + tig * 2;
                const int h = n >> 6, d = n & 63;
                float v0 = acc[mt][nt][hr * 2 + 0];
                float v1 = acc[mt][nt][hr * 2 + 1];
                if (which == 0) { v0 *= QSCALE; v1 *= QSCALE; }
                __half h0 = __float2half_rn(v0), h1 = __float2half_rn(v1);
                __half e0 = __float2half_rn(v0 - __half2float(h0));
                __half e1 = __float2half_rn(v1 - __half2float(h1));
                __half* hip = (which == 0) ? g_Qhi : (which == 1) ? g_Khi : g_Vhi;
                __half* lop = (which == 0) ? g_Qlo : (which == 1) ? g_Klo : g_Vlo;
                size_t idx = ((size_t)(bbp * NHEADS + h) * SEQ + sIdx) * DHEAD + d;
                *(__half2*)(hip + idx) = __halves2half2(h0, h1);
                *(__half2*)(lop + idx) = __halves2half2(e0, e1);
            }
        }
    }
}

// ---------------------------------------------------------------------------
// Flash attention, mma.sync + ldmatrix, software-pipelined:
// per tile: S(kt) MMA -> PV(kt-1) MMA (deferred, pha in regs) -> loads(kt+1)
// -> softmax(kt). Contiguous 48-MMA blocks keep tensor pipe fed across warps.
// CTA: 128 threads (4 warps), 64 query rows; 2 CTAs/SM.
// ---------------------------------------------------------------------------
constexpr int AST = 72;                       // smem row stride in halves
constexpr uint32_t QHI_O = 0;
constexpr uint32_t QLO_O = 9216;
constexpr uint32_t STG_O = 18432;
constexpr uint32_t STGSZ = 36864;             // KH/KL/VH/VL x 9216
constexpr uint32_t KH_O = 0, KL_O = 9216, VH_O = 18432, VL_O = 27648;
constexpr uint32_t ATTN_SMEM = STG_O + 2 * STGSZ;   // 92160

__global__ __launch_bounds__(128, 2)
void attn_mma_kernel(float* __restrict__ out)
{
    extern __shared__ uint8_t sm[];
    const uint32_t sb = smem_u32(sm);

    const int tid = threadIdx.x;
    const int lane = tid & 31;
    const int w = tid >> 5;                        // 0..3
    const int gid = lane >> 2;
    const int tig = lane & 3;
    const int bh = blockIdx.y;
    const int qt = (gridDim.x - 1) - blockIdx.x;   // heavy blocks first
    const int q0 = qt * 64;
    const int bb = bh >> 4, h = bh & 15;

    const uint32_t a_off = ((uint32_t)((lane & 15) * AST) + ((uint32_t)(lane >> 4) << 3)) * 2;
    const uint32_t b_off = ((uint32_t)(((lane & 7) + ((lane >> 4) << 3)) * AST) + (uint32_t)(lane & 8)) * 2;
    const uint32_t v_off = ((uint32_t)(((lane & 7) + ((lane >> 3) & 1) * 8) * AST) + ((uint32_t)(lane >> 4) << 3)) * 2;

    // ---- Q tile load (hi+lo): 64 rows x 64 d -----------------------------
#pragma unroll
    for (int comp = 0; comp < 2; comp++) {
#pragma unroll
        for (int it = 0; it < 4; it++) {
            int idx = tid + it * 128;
            int r = idx >> 3, g = idx & 7;
            uint32_t dst = sb + (comp ? QLO_O : QHI_O) + (uint32_t)(r * 144 + g * 16);
            const __half* src = (comp ? g_Qlo : g_Qhi) +
                                ((size_t)bh * SEQ + q0 + r) * DHEAD + g * 8;
            cp16(dst, src);
        }
    }

    auto load_kv = [&](int kt, int s) {
        uint32_t stage = sb + STG_O + (uint32_t)s * STGSZ;
        const __half* bases[4] = { g_Khi, g_Klo, g_Vhi, g_Vlo };
#pragma unroll
        for (int comp = 0; comp < 4; comp++) {
#pragma unroll
            for (int it = 0; it < 4; it++) {
                int idx = tid + it * 128;
                int r = idx >> 3, g = idx & 7;
                uint32_t dst = stage + (uint32_t)comp * 9216u + (uint32_t)(r * 144 + g * 16);
                const __half* src = bases[comp] +
                                    ((size_t)bh * SEQ + kt * 64 + r) * DHEAD + g * 8;
                cp16(dst, src);
            }
        }
    };

    // Q load + tile 0 in one commit group
    load_kv(0, 0);
    CP_COMMIT();
    CP_WAIT(0);
    __syncthreads();

    // ---- hoist Q fragments to registers (invariant across kt) -------------
    uint32_t qh[4][4], ql[4][4];
    {
        const uint32_t qbase = sb + (uint32_t)(w * 16 * AST) * 2 + a_off;
#pragma unroll
        for (int ks = 0; ks < 4; ks++) {
            ldsm4(qh[ks], qbase + QHI_O + ks * 32);
            ldsm4(ql[ks], qbase + QLO_O + ks * 32);
        }
    }

    float m0 = -1e30f, m1 = -1e30f, l0 = 0.f, l1 = 0.f;
    float oacc[8][4];
#pragma unroll
    for (int nt = 0; nt < 8; nt++)
#pragma unroll
        for (int j = 0; j < 4; j++) oacc[nt][j] = 0.f;

    const int ktmax = min(qt + 1, SEQ / 64 - 1);
    const int rowbase = w * 16 + gid;

    uint32_t pha[4][4];                 // deferred P fragments (valid when kt>0)

    for (int kt = 0; kt <= ktmax; kt++) {
        const int s = kt & 1;
        if (kt) { CP_WAIT(0); }          // stage s (loads kt) complete
        __syncthreads();                 // stage s visible to all warps

        const uint32_t stg  = sb + STG_O + (uint32_t)s * STGSZ;
        const uint32_t stgp = sb + STG_O + (uint32_t)(s ^ 1) * STGSZ;   // prev tile

        // ---- S = Q K^T (split fp16, ldmatrix) ----------------------------
        float sacc[8][4];
#pragma unroll
        for (int nt = 0; nt < 8; nt++)
#pragma unroll
            for (int j = 0; j < 4; j++) sacc[nt][j] = 0.f;

#pragma unroll
        for (int ks = 0; ks < 4; ks++) {
            const uint32_t kofs = (uint32_t)(ks * 32) + b_off;
#pragma unroll
            for (int np = 0; np < 4; np++) {
                uint32_t kh4[4], kl4[4];
                ldsm4(kh4, stg + KH_O + (uint32_t)(np * 16 * AST * 2) + kofs);
                ldsm4(kl4, stg + KL_O + (uint32_t)(np * 16 * AST * 2) + kofs);
                mma16816(sacc[2 * np],     qh[ks], kh4);
                mma16816(sacc[2 * np],     qh[ks], kl4);
                mma16816(sacc[2 * np],     ql[ks], kh4);
                mma16816(sacc[2 * np + 1], qh[ks], kh4 + 2);
                mma16816(sacc[2 * np + 1], qh[ks], kl4 + 2);
                mma16816(sacc[2 * np + 1], ql[ks], kh4 + 2);
            }
        }

        // ---- deferred PV(kt-1) from prev stage (before it's overwritten) --
        if (kt > 0) {
#pragma unroll
            for (int ks = 0; ks < 4; ks++) {
                const uint32_t srow = (uint32_t)(ks * 16 * AST * 2) + v_off;
#pragma unroll
                for (int np = 0; np < 4; np++) {
                    uint32_t vh4[4], vl4[4];
                    ldsm4t(vh4, stgp + VH_O + srow + (uint32_t)(np * 32));
                    ldsm4t(vl4, stgp + VL_O + srow + (uint32_t)(np * 32));
                    mma16816(oacc[2 * np],     pha[ks], vh4);
                    mma16816(oacc[2 * np],     pha[ks], vl4);
                    mma16816(oacc[2 * np + 1], pha[ks], vh4 + 2);
                    mma16816(oacc[2 * np + 1], pha[ks], vl4 + 2);
                }
            }
        }

        __syncthreads();                 // all warps done reading stage s^1
        if (kt < ktmax) {
            load_kv(kt + 1, s ^ 1);      // overlaps with softmax below
            CP_COMMIT();
        }

        // ---- mask: valid iff k <= q+1 (only kt >= qt tiles clip) ---------
        if (kt >= qt) {
            const int qg0 = q0 + rowbase, qg1 = qg0 + 8;
#pragma unroll
            for (int nt = 0; nt < 8; nt++) {
                const int c0 = kt * 64 + nt * 8 + tig * 2;
                if (c0     > qg0 + 1) sacc[nt][0] = -1e30f;
                if (c0 + 1 > qg0 + 1) sacc[nt][1] = -1e30f;
                if (c0     > qg1 + 1) sacc[nt][2] = -1e30f;
                if (c0 + 1 > qg1 + 1) sacc[nt][3] = -1e30f;
            }
        }

        // ---- online softmax, base-2 (MUFU ex2) ---------------------------
        // oacc already contains PV through kt-1, so scaling now is correct:
        // O_kt = (O_{kt-1} + P_{kt-1}V_{kt-1}) * sc_kt
        float r0 = -1e30f, r1 = -1e30f;
#pragma unroll
        for (int nt = 0; nt < 8; nt++) {
            r0 = fmaxf(r0, fmaxf(sacc[nt][0], sacc[nt][1]));
            r1 = fmaxf(r1, fmaxf(sacc[nt][2], sacc[nt][3]));
        }
        r0 = fmaxf(r0, __shfl_xor_sync(0xffffffffu, r0, 1));
        r0 = fmaxf(r0, __shfl_xor_sync(0xffffffffu, r0, 2));
        r1 = fmaxf(r1, __shfl_xor_sync(0xffffffffu, r1, 1));
        r1 = fmaxf(r1, __shfl_xor_sync(0xffffffffu, r1, 2));

        const float mn0 = fmaxf(m0, r0), mn1 = fmaxf(m1, r1);
        const float sc0 = fex2(m0 - mn0), sc1 = fex2(m1 - mn1);
        m0 = mn0; m1 = mn1;

        float rs0 = 0.f, rs1 = 0.f;
#pragma unroll
        for (int nt = 0; nt < 8; nt++) {
            float p0 = fex2(sacc[nt][0] - mn0);
            float p1 = fex2(sacc[nt][1] - mn0);
            float p2 = fex2(sacc[nt][2] - mn1);
            float p3 = fex2(sacc[nt][3] - mn1);
            rs0 += p0 + p1;
            rs1 += p2 + p3;
            const int ks = nt >> 1, hi2 = (nt & 1) << 1;
            pha[ks][hi2 + 0] = pack2h(__float2half_rn(p0), __float2half_rn(p1));  // row g
            pha[ks][hi2 + 1] = pack2h(__float2half_rn(p2), __float2half_rn(p3));  // row g+8
        }

        rs0 += __shfl_xor_sync(0xffffffffu, rs0, 1);
        rs0 += __shfl_xor_sync(0xffffffffu, rs0, 2);
        rs1 += __shfl_xor_sync(0xffffffffu, rs1, 1);
        rs1 += __shfl_xor_sync(0xffffffffu, rs1, 2);
        l0 = l0 * sc0 + rs0;
        l1 = l1 * sc1 + rs1;
#pragma unroll
        for (int nt = 0; nt < 8; nt++) {
            oacc[nt][0] *= sc0; oacc[nt][1] *= sc0;
            oacc[nt][2] *= sc1; oacc[nt][3] *= sc1;
        }
    }

    // ---- final deferred PV(ktmax): stage (ktmax&1) still intact -----------
    {
        const uint32_t stgf = sb + STG_O + (uint32_t)(ktmax & 1) * STGSZ;
#pragma unroll
        for (int ks = 0; ks < 4; ks++) {
            const uint32_t srow = (uint32_t)(ks * 16 * AST * 2) + v_off;
#pragma unroll
            for (int np = 0; np < 4; np++) {
                uint32_t vh4[4], vl4[4];
                ldsm4t(vh4, stgf + VH_O + srow + (uint32_t)(np * 32));
                ldsm4t(vl4, stgf + VL_O + srow + (uint32_t)(np * 32));
                mma16816(oacc[2 * np],     pha[ks], vh4);
                mma16816(oacc[2 * np],     pha[ks], vl4);
                mma16816(oacc[2 * np + 1], pha[ks], vh4 + 2);
                mma16816(oacc[2 * np + 1], pha[ks], vl4 + 2);
            }
        }
    }

    // ---- epilogue: out[b][s][h*64+d] --------------------------------------
    const float inv0 = 1.f / l0, inv1 = 1.f / l1;
    const int s0 = q0 + rowbase;
#pragma unroll
    for (int nt = 0; nt < 8; nt++) {
        const int d = h * DHEAD + nt * 8 + tig * 2;
        size_t i0 = ((size_t)(bb * SEQ + s0)) * DMODEL + d;
        size_t i1 = ((size_t)(bb * SEQ + s0 + 8)) * DMODEL + d;
        *(float2*)(out + i0) = make_float2(oacc[nt][0] * inv0, oacc[nt][1] * inv0);
        *(float2*)(out + i1) = make_float2(oacc[nt][2] * inv1, oacc[nt][3] * inv1);
    }
}

// ---------------------------------------------------------------------------
extern "C" void kernel_launch(void* const* d_in, const int* in_sizes, int n_in,
                              void* d_out, int out_size)
{
    const float* X  = (const float*)d_in[0];
    const float* Wq = (const float*)d_in[1];
    const float* Wk = (const float*)d_in[2];
    const float* Wv = (const float*)d_in[3];
    float* out = (float*)d_out;

    cudaFuncSetAttribute(qkv_mma_kernel,
                         cudaFuncAttributeMaxDynamicSharedMemorySize, GEMM_SMEM);
    cudaFuncSetAttribute(attn_mma_kernel,
                         cudaFuncAttributeMaxDynamicSharedMemorySize, ATTN_SMEM);

    split_x_kernel<<<(MTOT * DMODEL) / (256 * 4), 256>>>(X);
    split_wt_kernel<<<dim3(32, 32, 3), dim3(32, 8)>>>(Wq, Wk, Wv);

    dim3 ggrid(DMODEL / 128, MTOT / 128, 3);   // 8 x 64 x 3
    qkv_mma_kernel<<<ggrid, 256, GEMM_SMEM>>>();

    dim3 agrid(SEQ / 64, NBH);                 // 32 x 64
    attn_mma_kernel<<<agrid, 128, ATTN_SMEM>>>(out);
}

// round 12
// speedup vs baseline: 1.1794x; 1.1794x over previous
#include <cuda_runtime.h>
#include <cuda_fp16.h>
#include <cstdint>
#include <math.h>

#define BATCH  4
#define SEQ    2048
#define DMODEL 1024
#define NHEADS 16
#define DHEAD  64
#define NBH    (BATCH * NHEADS)   // 64
#define MTOT   (BATCH * SEQ)      // 8192

// ---------------- scratch (static device arrays; allocation-free) ----------
// Q,K,V all [bh][s][d] (d contiguous). Q pre-scaled by 0.125*log2(e).
__device__ __half g_Qhi[(size_t)NBH * SEQ * DHEAD];
__device__ __half g_Qlo[(size_t)NBH * SEQ * DHEAD];
__device__ __half g_Khi[(size_t)NBH * SEQ * DHEAD];
__device__ __half g_Klo[(size_t)NBH * SEQ * DHEAD];
__device__ __half g_Vhi[(size_t)NBH * SEQ * DHEAD];
__device__ __half g_Vlo[(size_t)NBH * SEQ * DHEAD];

__device__ __half g_Xhi[(size_t)MTOT * DMODEL];
__device__ __half g_Xlo[(size_t)MTOT * DMODEL];
__device__ __half g_WThi[(size_t)3 * DMODEL * DMODEL];  // [which][n][k]
__device__ __half g_WTlo[(size_t)3 * DMODEL * DMODEL];

// ---------------- helpers ---------------------------------------------------
__device__ __forceinline__ void cp16(uint32_t dst, const void* src) {
    asm volatile("cp.async.cg.shared.global [%0], [%1], 16;" :: "r"(dst), "l"(src));
}
#define CP_COMMIT() asm volatile("cp.async.commit_group;" ::: "memory")
#define CP_WAIT(n)  asm volatile("cp.async.wait_group %0;" :: "n"(n) : "memory")

__device__ __forceinline__ uint32_t smem_u32(const void* p) {
    uint32_t a;
    asm("{ .reg .u64 t; cvta.to.shared.u64 t, %1; cvt.u32.u64 %0, t; }" : "=r"(a) : "l"(p));
    return a;
}
__device__ __forceinline__ void mma16816(float* c, const uint32_t* a, const uint32_t* b) {
    asm volatile("mma.sync.aligned.m16n8k16.row.col.f32.f16.f16.f32 "
                 "{%0,%1,%2,%3}, {%4,%5,%6,%7}, {%8,%9}, {%0,%1,%2,%3};"
                 : "+f"(c[0]), "+f"(c[1]), "+f"(c[2]), "+f"(c[3])
                 : "r"(a[0]), "r"(a[1]), "r"(a[2]), "r"(a[3]), "r"(b[0]), "r"(b[1]));
}
__device__ __forceinline__ void ldsm4(uint32_t* r, uint32_t addr) {
    asm volatile("ldmatrix.sync.aligned.m8n8.x4.shared.b16 {%0,%1,%2,%3}, [%4];"
                 : "=r"(r[0]), "=r"(r[1]), "=r"(r[2]), "=r"(r[3]) : "r"(addr));
}
__device__ __forceinline__ void ldsm4t(uint32_t* r, uint32_t addr) {
    asm volatile("ldmatrix.sync.aligned.m8n8.x4.trans.shared.b16 {%0,%1,%2,%3}, [%4];"
                 : "=r"(r[0]), "=r"(r[1]), "=r"(r[2]), "=r"(r[3]) : "r"(addr));
}
__device__ __forceinline__ uint32_t pack2h(__half a, __half b) {
    __half2 t = __halves2half2(a, b);
    return *(uint32_t*)&t;
}
// MUFU exp2 (logits are pre-scaled to base-2 domain)
__device__ __forceinline__ float fex2(float x) {
    float r;
    asm("ex2.approx.f32 %0, %1;" : "=f"(r) : "f"(x));
    return r;
}

// ---------------- conversion kernels ---------------------------------------
__global__ void split_x_kernel(const float* __restrict__ X)
{
    size_t i = ((size_t)blockIdx.x * blockDim.x + threadIdx.x) * 4;
    float4 v = *(const float4*)(X + i);
    float f[4] = {v.x, v.y, v.z, v.w};
#pragma unroll
    for (int j = 0; j < 4; j++) {
        __half hi = __float2half_rn(f[j]);
        g_Xhi[i + j] = hi;
        g_Xlo[i + j] = __float2half_rn(f[j] - __half2float(hi));
    }
}

__global__ void split_wt_kernel(const float* __restrict__ Wq,
                                const float* __restrict__ Wk,
                                const float* __restrict__ Wv)
{
    __shared__ float t[32][33];
    const float* W = (blockIdx.z == 0) ? Wq : (blockIdx.z == 1) ? Wk : Wv;
    int tx = threadIdx.x, ty = threadIdx.y;
    int n = blockIdx.x * 32 + tx;
#pragma unroll
    for (int i = 0; i < 4; i++) {
        int k = blockIdx.y * 32 + ty + i * 8;
        t[ty + i * 8][tx] = W[(size_t)k * DMODEL + n];
    }
    __syncthreads();
    size_t base = (size_t)blockIdx.z * DMODEL * DMODEL;
#pragma unroll
    for (int i = 0; i < 4; i++) {
        int nn = blockIdx.x * 32 + ty + i * 8;
        int kk = blockIdx.y * 32 + tx;
        float f = t[tx][ty + i * 8];
        __half hi = __float2half_rn(f);
        g_WThi[base + (size_t)nn * DMODEL + kk] = hi;
        g_WTlo[base + (size_t)nn * DMODEL + kk] = __float2half_rn(f - __half2float(hi));
    }
}

// ---------------- mma.sync split-fp16 projection GEMM ----------------------
// Q/K: full 3-term split (hh+hl+lh). V (which==2): hh only — V error passes
// through attention linearly (~1.7e-4 rel), no softmax amplification.
constexpr int GKC = 32;
constexpr int NCHUNK = DMODEL / GKC;       // 32
constexpr int SST = 40;
constexpr uint32_t AHI = 0;
constexpr uint32_t ALO = 128 * SST * 2;
constexpr uint32_t BHI = 2 * 128 * SST * 2;
constexpr uint32_t BLO = 3 * 128 * SST * 2;
constexpr uint32_t STAGE = 4 * 128 * SST * 2;      // 40960
constexpr uint32_t GEMM_SMEM = 2 * STAGE;          // 81920

__global__ __launch_bounds__(256, 2)
void qkv_mma_kernel()
{
    extern __shared__ uint8_t sm[];
    const uint32_t sb = smem_u32(sm);

    const int tid = threadIdx.x;
    const int lane = tid & 31;
    const int warp = tid >> 5;
    const int wy = warp >> 2;
    const int wx = warp & 3;
    const int gid = lane >> 2;
    const int tig = lane & 3;

    const int which = blockIdx.z;
    const bool isV = (which == 2);
    const int n0 = blockIdx.x * 128;
    const int m0 = blockIdx.y * 128;

    const __half* __restrict__ WThi = g_WThi + (size_t)which * DMODEL * DMODEL;
    const __half* __restrict__ WTlo = g_WTlo + (size_t)which * DMODEL * DMODEL;

    const uint32_t a_off = ((uint32_t)((lane & 15) * SST) + ((uint32_t)(lane >> 4) << 3)) * 2;
    const uint32_t b_off = ((uint32_t)(((lane & 7) + ((lane >> 4) << 3)) * SST) + (uint32_t)(lane & 8)) * 2;

    auto load_chunk = [&](int c, int s) {
        const uint32_t stage = sb + (uint32_t)s * STAGE;
        const int c0 = c * GKC;
#pragma unroll
        for (int it = 0; it < 2; it++) {
            int idx = tid + it * 256;
            int r = idx >> 2, kg = idx & 3;
            uint32_t doff = (uint32_t)(r * SST * 2 + kg * 16);
            size_t asrc = (size_t)(m0 + r) * DMODEL + c0 + kg * 8;
            size_t bsrc = (size_t)(n0 + r) * DMODEL + c0 + kg * 8;
            cp16(stage + AHI + doff, g_Xhi + asrc);
            cp16(stage + BHI + doff, WThi + bsrc);
            if (!isV) {
                cp16(stage + ALO + doff, g_Xlo + asrc);
                cp16(stage + BLO + doff, WTlo + bsrc);
            }
        }
    };

    float acc[4][4][4];
#pragma unroll
    for (int mt = 0; mt < 4; mt++)
#pragma unroll
        for (int nt = 0; nt < 4; nt++)
#pragma unroll
            for (int j = 0; j < 4; j++) acc[mt][nt][j] = 0.f;

    load_chunk(0, 0);
    CP_COMMIT();

    for (int c = 0; c < NCHUNK; c++) {
        const int s = c & 1;
        if (c + 1 < NCHUNK) {
            load_chunk(c + 1, s ^ 1);
            CP_COMMIT();
            CP_WAIT(1);
        } else {
            CP_WAIT(0);
        }
        __syncthreads();

        const uint32_t stg = sb + (uint32_t)s * STAGE;

        if (!isV) {
#pragma unroll
            for (int ks = 0; ks < 2; ks++) {
                const uint32_t koff = (uint32_t)(ks * 32);
                uint32_t bh4[2][4], bl4[2][4];
#pragma unroll
                for (int np = 0; np < 2; np++) {
                    const uint32_t brow = (uint32_t)((wx * 32 + np * 16) * SST * 2);
                    ldsm4(bh4[np], stg + BHI + brow + koff + b_off);
                    ldsm4(bl4[np], stg + BLO + brow + koff + b_off);
                }
#pragma unroll
                for (int mt = 0; mt < 4; mt++) {
                    const uint32_t arow = (uint32_t)((wy * 64 + mt * 16) * SST * 2);
                    uint32_t ah[4], al[4];
                    ldsm4(ah, stg + AHI + arow + koff + a_off);
                    ldsm4(al, stg + ALO + arow + koff + a_off);
#pragma unroll
                    for (int np = 0; np < 2; np++) {
                        mma16816(acc[mt][2 * np],     ah, bh4[np]);
                        mma16816(acc[mt][2 * np],     ah, bl4[np]);
                        mma16816(acc[mt][2 * np],     al, bh4[np]);
                        mma16816(acc[mt][2 * np + 1], ah, bh4[np] + 2);
                        mma16816(acc[mt][2 * np + 1], ah, bl4[np] + 2);
                        mma16816(acc[mt][2 * np + 1], al, bh4[np] + 2);
                    }
                }
            }
        } else {
            // V: hh-only (2-term error analysis in header comment)
#pragma unroll
            for (int ks = 0; ks < 2; ks++) {
                const uint32_t koff = (uint32_t)(ks * 32);
                uint32_t bh4[2][4];
#pragma unroll
                for (int np = 0; np < 2; np++) {
                    const uint32_t brow = (uint32_t)((wx * 32 + np * 16) * SST * 2);
                    ldsm4(bh4[np], stg + BHI + brow + koff + b_off);
                }
#pragma unroll
                for (int mt = 0; mt < 4; mt++) {
                    const uint32_t arow = (uint32_t)((wy * 64 + mt * 16) * SST * 2);
                    uint32_t ah[4];
                    ldsm4(ah, stg + AHI + arow + koff + a_off);
#pragma unroll
                    for (int np = 0; np < 2; np++) {
                        mma16816(acc[mt][2 * np],     ah, bh4[np]);
                        mma16816(acc[mt][2 * np + 1], ah, bh4[np] + 2);
                    }
                }
            }
        }
        __syncthreads();
    }

    // ---- epilogue: emit fp16 hi/lo, all [bh][s][d] ------------------------
    const float QSCALE = 0.18033688011112042f;   // 0.125 * log2(e)
#pragma unroll
    for (int mt = 0; mt < 4; mt++) {
#pragma unroll
        for (int hr = 0; hr < 2; hr++) {
            const int m = m0 + wy * 64 + mt * 16 + gid + hr * 8;
            const int bbp = m >> 11;
            const int sIdx = m & 2047;
#pragma unroll
            for (int nt = 0; nt < 4; nt++) {
                const int n = n0 + wx * 32 + nt * 8 + tig * 2;
                const int h = n >> 6, d = n & 63;
                float v0 = acc[mt][nt][hr * 2 + 0];
                float v1 = acc[mt][nt][hr * 2 + 1];
                if (which == 0) { v0 *= QSCALE; v1 *= QSCALE; }
                __half h0 = __float2half_rn(v0), h1 = __float2half_rn(v1);
                __half e0 = __float2half_rn(v0 - __half2float(h0));
                __half e1 = __float2half_rn(v1 - __half2float(h1));
                __half* hip = (which == 0) ? g_Qhi : (which == 1) ? g_Khi : g_Vhi;
                __half* lop = (which == 0) ? g_Qlo : (which == 1) ? g_Klo : g_Vlo;
                size_t idx = ((size_t)(bbp * NHEADS + h) * SEQ + sIdx) * DHEAD + d;
                *(__half2*)(hip + idx) = __halves2half2(h0, h1);
                *(__half2*)(lop + idx) = __halves2half2(e0, e1);
            }
        }
    }
}

// ---------------------------------------------------------------------------
// Flash attention (R10 structure — best measured): mma.sync + ldmatrix,
// P and Q fragments in registers, V via ldmatrix.trans, loads issued at
// iteration top (max prefetch overlap). ex2-based softmax.
// CTA: 128 threads (4 warps), 64 query rows; 2 CTAs/SM.
// ---------------------------------------------------------------------------
constexpr int AST = 72;                       // smem row stride in halves
constexpr uint32_t QHI_O = 0;
constexpr uint32_t QLO_O = 9216;
constexpr uint32_t STG_O = 18432;
constexpr uint32_t STGSZ = 36864;             // KH/KL/VH/VL x 9216
constexpr uint32_t KH_O = 0, KL_O = 9216, VH_O = 18432, VL_O = 27648;
constexpr uint32_t ATTN_SMEM = STG_O + 2 * STGSZ;   // 92160

__global__ __launch_bounds__(128, 2)
void attn_mma_kernel(float* __restrict__ out)
{
    extern __shared__ uint8_t sm[];
    const uint32_t sb = smem_u32(sm);

    const int tid = threadIdx.x;
    const int lane = tid & 31;
    const int w = tid >> 5;                        // 0..3
    const int gid = lane >> 2;
    const int tig = lane & 3;
    const int bh = blockIdx.y;
    const int qt = (gridDim.x - 1) - blockIdx.x;   // heavy blocks first
    const int q0 = qt * 64;
    const int bb = bh >> 4, h = bh & 15;

    const uint32_t a_off = ((uint32_t)((lane & 15) * AST) + ((uint32_t)(lane >> 4) << 3)) * 2;
    const uint32_t b_off = ((uint32_t)(((lane & 7) + ((lane >> 4) << 3)) * AST) + (uint32_t)(lane & 8)) * 2;
    const uint32_t v_off = ((uint32_t)(((lane & 7) + ((lane >> 3) & 1) * 8) * AST) + ((uint32_t)(lane >> 4) << 3)) * 2;

    // ---- Q tile load (hi+lo): 64 rows x 64 d -----------------------------
#pragma unroll
    for (int comp = 0; comp < 2; comp++) {
#pragma unroll
        for (int it = 0; it < 4; it++) {
            int idx = tid + it * 128;
            int r = idx >> 3, g = idx & 7;
            uint32_t dst = sb + (comp ? QLO_O : QHI_O) + (uint32_t)(r * 144 + g * 16);
            const __half* src = (comp ? g_Qlo : g_Qhi) +
                                ((size_t)bh * SEQ + q0 + r) * DHEAD + g * 8;
            cp16(dst, src);
        }
    }

    auto load_kv = [&](int kt, int s) {
        uint32_t stage = sb + STG_O + (uint32_t)s * STGSZ;
        const __half* bases[4] = { g_Khi, g_Klo, g_Vhi, g_Vlo };
#pragma unroll
        for (int comp = 0; comp < 4; comp++) {
#pragma unroll
            for (int it = 0; it < 4; it++) {
                int idx = tid + it * 128;
                int r = idx >> 3, g = idx & 7;
                uint32_t dst = stage + (uint32_t)comp * 9216u + (uint32_t)(r * 144 + g * 16);
                const __half* src = bases[comp] +
                                    ((size_t)bh * SEQ + kt * 64 + r) * DHEAD + g * 8;
                cp16(dst, src);
            }
        }
    };

    load_kv(0, 0);
    CP_COMMIT();
    CP_WAIT(0);
    __syncthreads();

    // ---- hoist Q fragments to registers (invariant across kt) -------------
    uint32_t qh[4][4], ql[4][4];
    {
        const uint32_t qbase = sb + (uint32_t)(w * 16 * AST) * 2 + a_off;
#pragma unroll
        for (int ks = 0; ks < 4; ks++) {
            ldsm4(qh[ks], qbase + QHI_O + ks * 32);
            ldsm4(ql[ks], qbase + QLO_O + ks * 32);
        }
    }

    float m0 = -1e30f, m1 = -1e30f, l0 = 0.f, l1 = 0.f;
    float oacc[8][4];
#pragma unroll
    for (int nt = 0; nt < 8; nt++)
#pragma unroll
        for (int j = 0; j < 4; j++) oacc[nt][j] = 0.f;

    const int ktmax = min(qt + 1, SEQ / 64 - 1);
    const int rowbase = w * 16 + gid;

    for (int kt = 0; kt <= ktmax; kt++) {
        const int s = kt & 1;
        if (kt) __syncthreads();                  // stage s^1 free for reuse
        if (kt < ktmax) {
            load_kv(kt + 1, s ^ 1);
            CP_COMMIT();
            CP_WAIT(1);
        } else {
            CP_WAIT(0);
        }
        __syncthreads();

        const uint32_t stg = sb + STG_O + (uint32_t)s * STGSZ;

        // ---- S = Q K^T (split fp16, fp32 acc, ldmatrix B) ----------------
        float sacc[8][4];
#pragma unroll
        for (int nt = 0; nt < 8; nt++)
#pragma unroll
            for (int j = 0; j < 4; j++) sacc[nt][j] = 0.f;

#pragma unroll
        for (int ks = 0; ks < 4; ks++) {
            const uint32_t kofs = (uint32_t)(ks * 32) + b_off;
#pragma unroll
            for (int np = 0; np < 4; np++) {
                uint32_t kh4[4], kl4[4];
                ldsm4(kh4, stg + KH_O + (uint32_t)(np * 16 * AST * 2) + kofs);
                ldsm4(kl4, stg + KL_O + (uint32_t)(np * 16 * AST * 2) + kofs);
                mma16816(sacc[2 * np],     qh[ks], kh4);
                mma16816(sacc[2 * np],     qh[ks], kl4);
                mma16816(sacc[2 * np],     ql[ks], kh4);
                mma16816(sacc[2 * np + 1], qh[ks], kh4 + 2);
                mma16816(sacc[2 * np + 1], qh[ks], kl4 + 2);
                mma16816(sacc[2 * np + 1], ql[ks], kh4 + 2);
            }
        }

        // ---- mask: valid iff k <= q+1 (only kt >= qt tiles clip) ---------
        if (kt >= qt) {
            const int qg0 = q0 + rowbase, qg1 = qg0 + 8;
#pragma unroll
            for (int nt = 0; nt < 8; nt++) {
                const int c0 = kt * 64 + nt * 8 + tig * 2;
                if (c0     > qg0 + 1) sacc[nt][0] = -1e30f;
                if (c0 + 1 > qg0 + 1) sacc[nt][1] = -1e30f;
                if (c0     > qg1 + 1) sacc[nt][2] = -1e30f;
                if (c0 + 1 > qg1 + 1) sacc[nt][3] = -1e30f;
            }
        }

        // ---- online softmax, base-2 (MUFU ex2) ---------------------------
        float r0 = -1e30f, r1 = -1e30f;
#pragma unroll
        for (int nt = 0; nt < 8; nt++) {
            r0 = fmaxf(r0, fmaxf(sacc[nt][0], sacc[nt][1]));
            r1 = fmaxf(r1, fmaxf(sacc[nt][2], sacc[nt][3]));
        }
        r0 = fmaxf(r0, __shfl_xor_sync(0xffffffffu, r0, 1));
        r0 = fmaxf(r0, __shfl_xor_sync(0xffffffffu, r0, 2));
        r1 = fmaxf(r1, __shfl_xor_sync(0xffffffffu, r1, 1));
        r1 = fmaxf(r1, __shfl_xor_sync(0xffffffffu, r1, 2));

        const float mn0 = fmaxf(m0, r0), mn1 = fmaxf(m1, r1);
        const float sc0 = fex2(m0 - mn0), sc1 = fex2(m1 - mn1);
        m0 = mn0; m1 = mn1;

        // exp2 + pack P-hi directly into PV A-operand fragments
        uint32_t pha[4][4];
        float rs0 = 0.f, rs1 = 0.f;
#pragma unroll
        for (int nt = 0; nt < 8; nt++) {
            float p0 = fex2(sacc[nt][0] - mn0);
            float p1 = fex2(sacc[nt][1] - mn0);
            float p2 = fex2(sacc[nt][2] - mn1);
            float p3 = fex2(sacc[nt][3] - mn1);
            rs0 += p0 + p1;
            rs1 += p2 + p3;
            const int ks = nt >> 1, hi2 = (nt & 1) << 1;
            pha[ks][hi2 + 0] = pack2h(__float2half_rn(p0), __float2half_rn(p1));  // row g
            pha[ks][hi2 + 1] = pack2h(__float2half_rn(p2), __float2half_rn(p3));  // row g+8
        }

        rs0 += __shfl_xor_sync(0xffffffffu, rs0, 1);
        rs0 += __shfl_xor_sync(0xffffffffu, rs0, 2);
        rs1 += __shfl_xor_sync(0xffffffffu, rs1, 1);
        rs1 += __shfl_xor_sync(0xffffffffu, rs1, 2);
        l0 = l0 * sc0 + rs0;
        l1 = l1 * sc1 + rs1;
#pragma unroll
        for (int nt = 0; nt < 8; nt++) {
            oacc[nt][0] *= sc0; oacc[nt][1] *= sc0;
            oacc[nt][2] *= sc1; oacc[nt][3] *= sc1;
        }

        // ---- O += P V (P-hi x (V-hi + V-lo), trans-ldmatrix V) -----------
#pragma unroll
        for (int ks = 0; ks < 4; ks++) {
            const uint32_t srow = (uint32_t)(ks * 16 * AST * 2) + v_off;
#pragma unroll
            for (int np = 0; np < 4; np++) {
                uint32_t vh4[4], vl4[4];
                ldsm4t(vh4, stg + VH_O + srow + (uint32_t)(np * 32));
                ldsm4t(vl4, stg + VL_O + srow + (uint32_t)(np * 32));
                mma16816(oacc[2 * np],     pha[ks], vh4);
                mma16816(oacc[2 * np],     pha[ks], vl4);
                mma16816(oacc[2 * np + 1], pha[ks], vh4 + 2);
                mma16816(oacc[2 * np + 1], pha[ks], vl4 + 2);
            }
        }
    }

    // ---- epilogue: out[b][s][h*64+d] --------------------------------------
    const float inv0 = 1.f / l0, inv1 = 1.f / l1;
    const int s0 = q0 + rowbase;
#pragma unroll
    for (int nt = 0; nt < 8; nt++) {
        const int d = h * DHEAD + nt * 8 + tig * 2;
        size_t i0 = ((size_t)(bb * SEQ + s0)) * DMODEL + d;
        size_t i1 = ((size_t)(bb * SEQ + s0 + 8)) * DMODEL + d;
        *(float2*)(out + i0) = make_float2(oacc[nt][0] * inv0, oacc[nt][1] * inv0);
        *(float2*)(out + i1) = make_float2(oacc[nt][2] * inv1, oacc[nt][3] * inv1);
    }
}

// ---------------------------------------------------------------------------
extern "C" void kernel_launch(void* const* d_in, const int* in_sizes, int n_in,
                              void* d_out, int out_size)
{
    const float* X  = (const float*)d_in[0];
    const float* Wq = (const float*)d_in[1];
    const float* Wk = (const float*)d_in[2];
    const float* Wv = (const float*)d_in[3];
    float* out = (float*)d_out;

    cudaFuncSetAttribute(qkv_mma_kernel,
                         cudaFuncAttributeMaxDynamicSharedMemorySize, GEMM_SMEM);
    cudaFuncSetAttribute(attn_mma_kernel,
                         cudaFuncAttributeMaxDynamicSharedMemorySize, ATTN_SMEM);

    split_x_kernel<<<(MTOT * DMODEL) / (256 * 4), 256>>>(X);
    split_wt_kernel<<<dim3(32, 32, 3), dim3(32, 8)>>>(Wq, Wk, Wv);

    dim3 ggrid(DMODEL / 128, MTOT / 128, 3);   // 8 x 64 x 3
    qkv_mma_kernel<<<ggrid, 256, GEMM_SMEM>>>();

    dim3 agrid(SEQ / 64, NBH);                 // 32 x 64
    attn_mma_kernel<<<agrid, 128, ATTN_SMEM>>>(out);
}

// round 15
// speedup vs baseline: 1.3223x; 1.1211x over previous
#include <cuda_runtime.h>
#include <cuda_fp16.h>
#include <cstdint>
#include <math.h>

#define BATCH  4
#define SEQ    2048
#define DMODEL 1024
#define NHEADS 16
#define DHEAD  64
#define NBH    (BATCH * NHEADS)   // 64
#define MTOT   (BATCH * SEQ)      // 8192

// ---------------- scratch (static device arrays; allocation-free) ----------
// Q,K,V all [bh][s][d] (d contiguous). Q pre-scaled by 0.125*log2(e).
__device__ __half g_Qhi[(size_t)NBH * SEQ * DHEAD];
__device__ __half g_Qlo[(size_t)NBH * SEQ * DHEAD];
__device__ __half g_Khi[(size_t)NBH * SEQ * DHEAD];
__device__ __half g_Klo[(size_t)NBH * SEQ * DHEAD];
__device__ __half g_Vhi[(size_t)NBH * SEQ * DHEAD];

__device__ __half g_Xhi[(size_t)MTOT * DMODEL];
__device__ __half g_Xlo[(size_t)MTOT * DMODEL];
__device__ __half g_WThi[(size_t)3 * DMODEL * DMODEL];  // [which][n][k]
__device__ __half g_WTlo[(size_t)3 * DMODEL * DMODEL];

// ---------------- helpers ---------------------------------------------------
__device__ __forceinline__ void cp16(uint32_t dst, const void* src) {
    asm volatile("cp.async.cg.shared.global [%0], [%1], 16;" :: "r"(dst), "l"(src));
}
#define CP_COMMIT() asm volatile("cp.async.commit_group;" ::: "memory")
#define CP_WAIT(n)  asm volatile("cp.async.wait_group %0;" :: "n"(n) : "memory")

__device__ __forceinline__ uint32_t smem_u32(const void* p) {
    uint32_t a;
    asm("{ .reg .u64 t; cvta.to.shared.u64 t, %1; cvt.u32.u64 %0, t; }" : "=r"(a) : "l"(p));
    return a;
}
__device__ __forceinline__ void mma16816(float* c, const uint32_t* a, const uint32_t* b) {
    asm volatile("mma.sync.aligned.m16n8k16.row.col.f32.f16.f16.f32 "
                 "{%0,%1,%2,%3}, {%4,%5,%6,%7}, {%8,%9}, {%0,%1,%2,%3};"
                 : "+f"(c[0]), "+f"(c[1]), "+f"(c[2]), "+f"(c[3])
                 : "r"(a[0]), "r"(a[1]), "r"(a[2]), "r"(a[3]), "r"(b[0]), "r"(b[1]));
}
__device__ __forceinline__ void ldsm4(uint32_t* r, uint32_t addr) {
    asm volatile("ldmatrix.sync.aligned.m8n8.x4.shared.b16 {%0,%1,%2,%3}, [%4];"
                 : "=r"(r[0]), "=r"(r[1]), "=r"(r[2]), "=r"(r[3]) : "r"(addr));
}
__device__ __forceinline__ void ldsm4t(uint32_t* r, uint32_t addr) {
    asm volatile("ldmatrix.sync.aligned.m8n8.x4.trans.shared.b16 {%0,%1,%2,%3}, [%4];"
                 : "=r"(r[0]), "=r"(r[1]), "=r"(r[2]), "=r"(r[3]) : "r"(addr));
}
__device__ __forceinline__ uint32_t pack2h(__half a, __half b) {
    __half2 t = __halves2half2(a, b);
    return *(uint32_t*)&t;
}
// MUFU exp2 (logits are pre-scaled to base-2 domain)
__device__ __forceinline__ float fex2(float x) {
    float r;
    asm("ex2.approx.f32 %0, %1;" : "=f"(r) : "f"(x));
    return r;
}

// ---------------- conversion kernels ---------------------------------------
__global__ void split_x_kernel(const float* __restrict__ X)
{
    size_t i = ((size_t)blockIdx.x * blockDim.x + threadIdx.x) * 4;
    float4 v = *(const float4*)(X + i);
    float f[4] = {v.x, v.y, v.z, v.w};
#pragma unroll
    for (int j = 0; j < 4; j++) {
        __half hi = __float2half_rn(f[j]);
        g_Xhi[i + j] = hi;
        g_Xlo[i + j] = __float2half_rn(f[j] - __half2float(hi));
    }
}

__global__ void split_wt_kernel(const float* __restrict__ Wq,
                                const float* __restrict__ Wk,
                                const float* __restrict__ Wv)
{
    __shared__ float t[32][33];
    const float* W = (blockIdx.z == 0) ? Wq : (blockIdx.z == 1) ? Wk : Wv;
    int tx = threadIdx.x, ty = threadIdx.y;
    int n = blockIdx.x * 32 + tx;
#pragma unroll
    for (int i = 0; i < 4; i++) {
        int k = blockIdx.y * 32 + ty + i * 8;
        t[ty + i * 8][tx] = W[(size_t)k * DMODEL + n];
    }
    __syncthreads();
    size_t base = (size_t)blockIdx.z * DMODEL * DMODEL;
#pragma unroll
    for (int i = 0; i < 4; i++) {
        int nn = blockIdx.x * 32 + ty + i * 8;
        int kk = blockIdx.y * 32 + tx;
        float f = t[tx][ty + i * 8];
        __half hi = __float2half_rn(f);
        g_WThi[base + (size_t)nn * DMODEL + kk] = hi;
        g_WTlo[base + (size_t)nn * DMODEL + kk] = __float2half_rn(f - __half2float(hi));
    }
}

// ---------------- mma.sync split-fp16 projection GEMM ----------------------
// Q/K: full 3-term split (hh+hl+lh). V (which==2): hh only.
constexpr int GKC = 32;
constexpr int NCHUNK = DMODEL / GKC;       // 32
constexpr int SST = 40;
constexpr uint32_t AHI = 0;
constexpr uint32_t ALO = 128 * SST * 2;
constexpr uint32_t BHI = 2 * 128 * SST * 2;
constexpr uint32_t BLO = 3 * 128 * SST * 2;
constexpr uint32_t STAGE = 4 * 128 * SST * 2;      // 40960
constexpr uint32_t GEMM_SMEM = 2 * STAGE;          // 81920

__global__ __launch_bounds__(256, 2)
void qkv_mma_kernel()
{
    extern __shared__ uint8_t sm[];
    const uint32_t sb = smem_u32(sm);

    const int tid = threadIdx.x;
    const int lane = tid & 31;
    const int warp = tid >> 5;
    const int wy = warp >> 2;
    const int wx = warp & 3;
    const int gid = lane >> 2;
    const int tig = lane & 3;

    const int which = blockIdx.z;
    const bool isV = (which == 2);
    const int n0 = blockIdx.x * 128;
    const int m0 = blockIdx.y * 128;

    const __half* __restrict__ WThi = g_WThi + (size_t)which * DMODEL * DMODEL;
    const __half* __restrict__ WTlo = g_WTlo + (size_t)which * DMODEL * DMODEL;

    const uint32_t a_off = ((uint32_t)((lane & 15) * SST) + ((uint32_t)(lane >> 4) << 3)) * 2;
    const uint32_t b_off = ((uint32_t)(((lane & 7) + ((lane >> 4) << 3)) * SST) + (uint32_t)(lane & 8)) * 2;

    auto load_chunk = [&](int c, int s) {
        const uint32_t stage = sb + (uint32_t)s * STAGE;
        const int c0 = c * GKC;
#pragma unroll
        for (int it = 0; it < 2; it++) {
            int idx = tid + it * 256;
            int r = idx >> 2, kg = idx & 3;
            uint32_t doff = (uint32_t)(r * SST * 2 + kg * 16);
            size_t asrc = (size_t)(m0 + r) * DMODEL + c0 + kg * 8;
            size_t bsrc = (size_t)(n0 + r) * DMODEL + c0 + kg * 8;
            cp16(stage + AHI + doff, g_Xhi + asrc);
            cp16(stage + BHI + doff, WThi + bsrc);
            if (!isV) {
                cp16(stage + ALO + doff, g_Xlo + asrc);
                cp16(stage + BLO + doff, WTlo + bsrc);
            }
        }
    };

    float acc[4][4][4];
#pragma unroll
    for (int mt = 0; mt < 4; mt++)
#pragma unroll
        for (int nt = 0; nt < 4; nt++)
#pragma unroll
            for (int j = 0; j < 4; j++) acc[mt][nt][j] = 0.f;

    load_chunk(0, 0);
    CP_COMMIT();

    for (int c = 0; c < NCHUNK; c++) {
        const int s = c & 1;
        if (c + 1 < NCHUNK) {
            load_chunk(c + 1, s ^ 1);
            CP_COMMIT();
            CP_WAIT(1);
        } else {
            CP_WAIT(0);
        }
        __syncthreads();

        const uint32_t stg = sb + (uint32_t)s * STAGE;

        if (!isV) {
#pragma unroll
            for (int ks = 0; ks < 2; ks++) {
                const uint32_t koff = (uint32_t)(ks * 32);
                uint32_t bh4[2][4], bl4[2][4];
#pragma unroll
                for (int np = 0; np < 2; np++) {
                    const uint32_t brow = (uint32_t)((wx * 32 + np * 16) * SST * 2);
                    ldsm4(bh4[np], stg + BHI + brow + koff + b_off);
                    ldsm4(bl4[np], stg + BLO + brow + koff + b_off);
                }
#pragma unroll
                for (int mt = 0; mt < 4; mt++) {
                    const uint32_t arow = (uint32_t)((wy * 64 + mt * 16) * SST * 2);
                    uint32_t ah[4], al[4];
                    ldsm4(ah, stg + AHI + arow + koff + a_off);
                    ldsm4(al, stg + ALO + arow + koff + a_off);
#pragma unroll
                    for (int np = 0; np < 2; np++) {
                        mma16816(acc[mt][2 * np],     ah, bh4[np]);
                        mma16816(acc[mt][2 * np],     ah, bl4[np]);
                        mma16816(acc[mt][2 * np],     al, bh4[np]);
                        mma16816(acc[mt][2 * np + 1], ah, bh4[np] + 2);
                        mma16816(acc[mt][2 * np + 1], ah, bl4[np] + 2);
                        mma16816(acc[mt][2 * np + 1], al, bh4[np] + 2);
                    }
                }
            }
        } else {
#pragma unroll
            for (int ks = 0; ks < 2; ks++) {
                const uint32_t koff = (uint32_t)(ks * 32);
                uint32_t bh4[2][4];
#pragma unroll
                for (int np = 0; np < 2; np++) {
                    const uint32_t brow = (uint32_t)((wx * 32 + np * 16) * SST * 2);
                    ldsm4(bh4[np], stg + BHI + brow + koff + b_off);
                }
#pragma unroll
                for (int mt = 0; mt < 4; mt++) {
                    const uint32_t arow = (uint32_t)((wy * 64 + mt * 16) * SST * 2);
                    uint32_t ah[4];
                    ldsm4(ah, stg + AHI + arow + koff + a_off);
#pragma unroll
                    for (int np = 0; np < 2; np++) {
                        mma16816(acc[mt][2 * np],     ah, bh4[np]);
                        mma16816(acc[mt][2 * np + 1], ah, bh4[np] + 2);
                    }
                }
            }
        }
        __syncthreads();
    }

    // ---- epilogue: emit fp16 hi(/lo for Q,K), all [bh][s][d] --------------
    const float QSCALE = 0.18033688011112042f;   // 0.125 * log2(e)
#pragma unroll
    for (int mt = 0; mt < 4; mt++) {
#pragma unroll
        for (int hr = 0; hr < 2; hr++) {
            const int m = m0 + wy * 64 + mt * 16 + gid + hr * 8;
            const int bbp = m >> 11;
            const int sIdx = m & 2047;
#pragma unroll
            for (int nt = 0; nt < 4; nt++) {
                const int n = n0 + wx * 32 + nt * 8 + tig * 2;
                const int h = n >> 6, d = n & 63;
                float v0 = acc[mt][nt][hr * 2 + 0];
                float v1 = acc[mt][nt][hr * 2 + 1];
                if (which == 0) { v0 *= QSCALE; v1 *= QSCALE; }
                __half h0 = __float2half_rn(v0), h1 = __float2half_rn(v1);
                __half* hip = (which == 0) ? g_Qhi : (which == 1) ? g_Khi : g_Vhi;
                size_t idx = ((size_t)(bbp * NHEADS + h) * SEQ + sIdx) * DHEAD + d;
                *(__half2*)(hip + idx) = __halves2half2(h0, h1);
                if (!isV) {
                    __half e0 = __float2half_rn(v0 - __half2float(h0));
                    __half e1 = __float2half_rn(v1 - __half2float(h1));
                    __half* lop = (which == 0) ? g_Qlo : g_Klo;
                    *(__half2*)(lop + idx) = __halves2half2(e0, e1);
                }
            }
        }
    }
}

// ---------------------------------------------------------------------------
// Flash attention: mma.sync + ldmatrix, Q/P fragments in registers, V-hi only
// (V-lo dropped; its info content ~ the V error already accepted). Smaller
// stages (K-hi/K-lo/V-hi) => 3 CTAs/SM.
// CTA: 128 threads (4 warps), 64 query rows.
// ---------------------------------------------------------------------------
constexpr int AST = 72;                       // smem row stride in halves
constexpr uint32_t QHI_O = 0;
constexpr uint32_t QLO_O = 9216;
constexpr uint32_t STG_O = 18432;
constexpr uint32_t STGSZ = 27648;             // KH/KL/VH x 9216
constexpr uint32_t KH_O = 0, KL_O = 9216, VH_O = 18432;
constexpr uint32_t ATTN_SMEM = STG_O + 2 * STGSZ;   // 73728 -> 3 CTAs/SM

__global__ __launch_bounds__(128, 3)
void attn_mma_kernel(float* __restrict__ out)
{
    extern __shared__ uint8_t sm[];
    const uint32_t sb = smem_u32(sm);

    const int tid = threadIdx.x;
    const int lane = tid & 31;
    const int w = tid >> 5;                        // 0..3
    const int gid = lane >> 2;
    const int tig = lane & 3;
    const int bh = blockIdx.y;
    const int qt = (gridDim.x - 1) - blockIdx.x;   // heavy blocks first
    const int q0 = qt * 64;
    const int bb = bh >> 4, h = bh & 15;

    const uint32_t a_off = ((uint32_t)((lane & 15) * AST) + ((uint32_t)(lane >> 4) << 3)) * 2;
    const uint32_t b_off = ((uint32_t)(((lane & 7) + ((lane >> 4) << 3)) * AST) + (uint32_t)(lane & 8)) * 2;
    const uint32_t v_off = ((uint32_t)(((lane & 7) + ((lane >> 3) & 1) * 8) * AST) + ((uint32_t)(lane >> 4) << 3)) * 2;

    // ---- Q tile load (hi+lo): 64 rows x 64 d -----------------------------
#pragma unroll
    for (int comp = 0; comp < 2; comp++) {
#pragma unroll
        for (int it = 0; it < 4; it++) {
            int idx = tid + it * 128;
            int r = idx >> 3, g = idx & 7;
            uint32_t dst = sb + (comp ? QLO_O : QHI_O) + (uint32_t)(r * 144 + g * 16);
            const __half* src = (comp ? g_Qlo : g_Qhi) +
                                ((size_t)bh * SEQ + q0 + r) * DHEAD + g * 8;
            cp16(dst, src);
        }
    }

    auto load_kv = [&](int kt, int s) {
        uint32_t stage = sb + STG_O + (uint32_t)s * STGSZ;
        const __half* bases[3] = { g_Khi, g_Klo, g_Vhi };
#pragma unroll
        for (int comp = 0; comp < 3; comp++) {
#pragma unroll
            for (int it = 0; it < 4; it++) {
                int idx = tid + it * 128;
                int r = idx >> 3, g = idx & 7;
                uint32_t dst = stage + (uint32_t)comp * 9216u + (uint32_t)(r * 144 + g * 16);
                const __half* src = bases[comp] +
                                    ((size_t)bh * SEQ + kt * 64 + r) * DHEAD + g * 8;
                cp16(dst, src);
            }
        }
    };

    load_kv(0, 0);
    CP_COMMIT();
    CP_WAIT(0);
    __syncthreads();

    // ---- hoist Q fragments to registers (invariant across kt) -------------
    uint32_t qh[4][4], ql[4][4];
    {
        const uint32_t qbase = sb + (uint32_t)(w * 16 * AST) * 2 + a_off;
#pragma unroll
        for (int ks = 0; ks < 4; ks++) {
            ldsm4(qh[ks], qbase + QHI_O + ks * 32);
            ldsm4(ql[ks], qbase + QLO_O + ks * 32);
        }
    }

    float m0 = -1e30f, m1 = -1e30f, l0 = 0.f, l1 = 0.f;
    float oacc[8][4];
#pragma unroll
    for (int nt = 0; nt < 8; nt++)
#pragma unroll
        for (int j = 0; j < 4; j++) oacc[nt][j] = 0.f;

    const int ktmax = min(qt + 1, SEQ / 64 - 1);
    const int rowbase = w * 16 + gid;

    for (int kt = 0; kt <= ktmax; kt++) {
        const int s = kt & 1;
        if (kt) __syncthreads();                  // stage s^1 free for reuse
        if (kt < ktmax) {
            load_kv(kt + 1, s ^ 1);
            CP_COMMIT();
            CP_WAIT(1);
        } else {
            CP_WAIT(0);
        }
        __syncthreads();

        const uint32_t stg = sb + STG_O + (uint32_t)s * STGSZ;

        // ---- S = Q K^T (split fp16, fp32 acc, ldmatrix B) ----------------
        float sacc[8][4];
#pragma unroll
        for (int nt = 0; nt < 8; nt++)
#pragma unroll
            for (int j = 0; j < 4; j++) sacc[nt][j] = 0.f;

#pragma unroll
        for (int ks = 0; ks < 4; ks++) {
            const uint32_t kofs = (uint32_t)(ks * 32) + b_off;
#pragma unroll
            for (int np = 0; np < 4; np++) {
                uint32_t kh4[4], kl4[4];
                ldsm4(kh4, stg + KH_O + (uint32_t)(np * 16 * AST * 2) + kofs);
                ldsm4(kl4, stg + KL_O + (uint32_t)(np * 16 * AST * 2) + kofs);
                mma16816(sacc[2 * np],     qh[ks], kh4);
                mma16816(sacc[2 * np],     qh[ks], kl4);
                mma16816(sacc[2 * np],     ql[ks], kh4);
                mma16816(sacc[2 * np + 1], qh[ks], kh4 + 2);
                mma16816(sacc[2 * np + 1], qh[ks], kl4 + 2);
                mma16816(sacc[2 * np + 1], ql[ks], kh4 + 2);
            }
        }

        // ---- mask: valid iff k <= q+1 (only kt >= qt tiles clip) ---------
        if (kt >= qt) {
            const int qg0 = q0 + rowbase, qg1 = qg0 + 8;
#pragma unroll
            for (int nt = 0; nt < 8; nt++) {
                const int c0 = kt * 64 + nt * 8 + tig * 2;
                if (c0     > qg0 + 1) sacc[nt][0] = -1e30f;
                if (c0 + 1 > qg0 + 1) sacc[nt][1] = -1e30f;
                if (c0     > qg1 + 1) sacc[nt][2] = -1e30f;
                if (c0 + 1 > qg1 + 1) sacc[nt][3] = -1e30f;
            }
        }

        // ---- online softmax, base-2 (MUFU ex2) ---------------------------
        float r0 = -1e30f, r1 = -1e30f;
#pragma unroll
        for (int nt = 0; nt < 8; nt++) {
            r0 = fmaxf(r0, fmaxf(sacc[nt][0], sacc[nt][1]));
            r1 = fmaxf(r1, fmaxf(sacc[nt][2], sacc[nt][3]));
        }
        r0 = fmaxf(r0, __shfl_xor_sync(0xffffffffu, r0, 1));
        r0 = fmaxf(r0, __shfl_xor_sync(0xffffffffu, r0, 2));
        r1 = fmaxf(r1, __shfl_xor_sync(0xffffffffu, r1, 1));
        r1 = fmaxf(r1, __shfl_xor_sync(0xffffffffu, r1, 2));

        const float mn0 = fmaxf(m0, r0), mn1 = fmaxf(m1, r1);
        const float sc0 = fex2(m0 - mn0), sc1 = fex2(m1 - mn1);
        m0 = mn0; m1 = mn1;

        // exp2 + pack P-hi directly into PV A-operand fragments
        uint32_t pha[4][4];
        float rs0 = 0.f, rs1 = 0.f;
#pragma unroll
        for (int nt = 0; nt < 8; nt++) {
            float p0 = fex2(sacc[nt][0] - mn0);
            float p1 = fex2(sacc[nt][1] - mn0);
            float p2 = fex2(sacc[nt][2] - mn1);
            float p3 = fex2(sacc[nt][3] - mn1);
            rs0 += p0 + p1;
            rs1 += p2 + p3;
            const int ks = nt >> 1, hi2 = (nt & 1) << 1;
            pha[ks][hi2 + 0] = pack2h(__float2half_rn(p0), __float2half_rn(p1));  // row g
            pha[ks][hi2 + 1] = pack2h(__float2half_rn(p2), __float2half_rn(p3));  // row g+8
        }

        rs0 += __shfl_xor_sync(0xffffffffu, rs0, 1);
        rs0 += __shfl_xor_sync(0xffffffffu, rs0, 2);
        rs1 += __shfl_xor_sync(0xffffffffu, rs1, 1);
        rs1 += __shfl_xor_sync(0xffffffffu, rs1, 2);
        l0 = l0 * sc0 + rs0;
        l1 = l1 * sc1 + rs1;
#pragma unroll
        for (int nt = 0; nt < 8; nt++) {
            oacc[nt][0] *= sc0; oacc[nt][1] *= sc0;
            oacc[nt][2] *= sc1; oacc[nt][3] *= sc1;
        }

        // ---- O += P V (P-hi x V-hi, trans-ldmatrix V) --------------------
#pragma unroll
        for (int ks = 0; ks < 4; ks++) {
            const uint32_t srow = (uint32_t)(ks * 16 * AST * 2) + v_off;
#pragma unroll
            for (int np = 0; np < 4; np++) {
                uint32_t vh4[4];
                ldsm4t(vh4, stg + VH_O + srow + (uint32_t)(np * 32));
                mma16816(oacc[2 * np],     pha[ks], vh4);
                mma16816(oacc[2 * np + 1], pha[ks], vh4 + 2);
            }
        }
    }

    // ---- epilogue: out[b][s][h*64+d] --------------------------------------
    const float inv0 = 1.f / l0, inv1 = 1.f / l1;
    const int s0 = q0 + rowbase;
#pragma unroll
    for (int nt = 0; nt < 8; nt++) {
        const int d = h * DHEAD + nt * 8 + tig * 2;
        size_t i0 = ((size_t)(bb * SEQ + s0)) * DMODEL + d;
        size_t i1 = ((size_t)(bb * SEQ + s0 + 8)) * DMODEL + d;
        *(float2*)(out + i0) = make_float2(oacc[nt][0] * inv0, oacc[nt][1] * inv0);
        *(float2*)(out + i1) = make_float2(oacc[nt][2] * inv1, oacc[nt][3] * inv1);
    }
}

// ---------------------------------------------------------------------------
extern "C" void kernel_launch(void* const* d_in, const int* in_sizes, int n_in,
                              void* d_out, int out_size)
{
    const float* X  = (const float*)d_in[0];
    const float* Wq = (const float*)d_in[1];
    const float* Wk = (const float*)d_in[2];
    const float* Wv = (const float*)d_in[3];
    float* out = (float*)d_out;

    cudaFuncSetAttribute(qkv_mma_kernel,
                         cudaFuncAttributeMaxDynamicSharedMemorySize, GEMM_SMEM);
    cudaFuncSetAttribute(attn_mma_kernel,
                         cudaFuncAttributeMaxDynamicSharedMemorySize, ATTN_SMEM);

    split_x_kernel<<<(MTOT * DMODEL) / (256 * 4), 256>>>(X);
    split_wt_kernel<<<dim3(32, 32, 3), dim3(32, 8)>>>(Wq, Wk, Wv);

    dim3 ggrid(DMODEL / 128, MTOT / 128, 3);   // 8 x 64 x 3
    qkv_mma_kernel<<<ggrid, 256, GEMM_SMEM>>>();

    dim3 agrid(SEQ / 64, NBH);                 // 32 x 64
    attn_mma_kernel<<<agrid, 128, ATTN_SMEM>>>(out);
}

// round 16
// speedup vs baseline: 1.3845x; 1.0471x over previous
#include <cuda_runtime.h>
#include <cuda_fp16.h>
#include <cstdint>
#include <math.h>

#define BATCH  4
#define SEQ    2048
#define DMODEL 1024
#define NHEADS 16
#define DHEAD  64
#define NBH    (BATCH * NHEADS)   // 64
#define MTOT   (BATCH * SEQ)      // 8192

// ---------------- scratch (static device arrays; allocation-free) ----------
// Q,K,V all [bh][s][d] (d contiguous). Q pre-scaled by 0.125*log2(e).
__device__ __half g_Qhi[(size_t)NBH * SEQ * DHEAD];
__device__ __half g_Qlo[(size_t)NBH * SEQ * DHEAD];
__device__ __half g_Khi[(size_t)NBH * SEQ * DHEAD];
__device__ __half g_Klo[(size_t)NBH * SEQ * DHEAD];
__device__ __half g_Vhi[(size_t)NBH * SEQ * DHEAD];

__device__ __half g_Xhi[(size_t)MTOT * DMODEL];
__device__ __half g_Xlo[(size_t)MTOT * DMODEL];
__device__ __half g_WThi[(size_t)3 * DMODEL * DMODEL];  // [which][n][k]
__device__ __half g_WTlo[(size_t)3 * DMODEL * DMODEL];

// ---------------- helpers ---------------------------------------------------
__device__ __forceinline__ void cp16(uint32_t dst, const void* src) {
    asm volatile("cp.async.cg.shared.global [%0], [%1], 16;" :: "r"(dst), "l"(src));
}
#define CP_COMMIT() asm volatile("cp.async.commit_group;" ::: "memory")
#define CP_WAIT(n)  asm volatile("cp.async.wait_group %0;" :: "n"(n) : "memory")

__device__ __forceinline__ uint32_t smem_u32(const void* p) {
    uint32_t a;
    asm("{ .reg .u64 t; cvta.to.shared.u64 t, %1; cvt.u32.u64 %0, t; }" : "=r"(a) : "l"(p));
    return a;
}
__device__ __forceinline__ void mma16816(float* c, const uint32_t* a, const uint32_t* b) {
    asm volatile("mma.sync.aligned.m16n8k16.row.col.f32.f16.f16.f32 "
                 "{%0,%1,%2,%3}, {%4,%5,%6,%7}, {%8,%9}, {%0,%1,%2,%3};"
                 : "+f"(c[0]), "+f"(c[1]), "+f"(c[2]), "+f"(c[3])
                 : "r"(a[0]), "r"(a[1]), "r"(a[2]), "r"(a[3]), "r"(b[0]), "r"(b[1]));
}
__device__ __forceinline__ void ldsm4(uint32_t* r, uint32_t addr) {
    asm volatile("ldmatrix.sync.aligned.m8n8.x4.shared.b16 {%0,%1,%2,%3}, [%4];"
                 : "=r"(r[0]), "=r"(r[1]), "=r"(r[2]), "=r"(r[3]) : "r"(addr));
}
__device__ __forceinline__ void ldsm4t(uint32_t* r, uint32_t addr) {
    asm volatile("ldmatrix.sync.aligned.m8n8.x4.trans.shared.b16 {%0,%1,%2,%3}, [%4];"
                 : "=r"(r[0]), "=r"(r[1]), "=r"(r[2]), "=r"(r[3]) : "r"(addr));
}
__device__ __forceinline__ uint32_t pack2h(__half a, __half b) {
    __half2 t = __halves2half2(a, b);
    return *(uint32_t*)&t;
}
// MUFU exp2 (logits are pre-scaled to base-2 domain)
__device__ __forceinline__ float fex2(float x) {
    float r;
    asm("ex2.approx.f32 %0, %1;" : "=f"(r) : "f"(x));
    return r;
}

// ---------------- conversion kernels ---------------------------------------
__global__ void split_x_kernel(const float* __restrict__ X)
{
    size_t i = ((size_t)blockIdx.x * blockDim.x + threadIdx.x) * 4;
    float4 v = *(const float4*)(X + i);
    float f[4] = {v.x, v.y, v.z, v.w};
#pragma unroll
    for (int j = 0; j < 4; j++) {
        __half hi = __float2half_rn(f[j]);
        g_Xhi[i + j] = hi;
        g_Xlo[i + j] = __float2half_rn(f[j] - __half2float(hi));
    }
}

__global__ void split_wt_kernel(const float* __restrict__ Wq,
                                const float* __restrict__ Wk,
                                const float* __restrict__ Wv)
{
    __shared__ float t[32][33];
    const float* W = (blockIdx.z == 0) ? Wq : (blockIdx.z == 1) ? Wk : Wv;
    int tx = threadIdx.x, ty = threadIdx.y;
    int n = blockIdx.x * 32 + tx;
#pragma unroll
    for (int i = 0; i < 4; i++) {
        int k = blockIdx.y * 32 + ty + i * 8;
        t[ty + i * 8][tx] = W[(size_t)k * DMODEL + n];
    }
    __syncthreads();
    size_t base = (size_t)blockIdx.z * DMODEL * DMODEL;
#pragma unroll
    for (int i = 0; i < 4; i++) {
        int nn = blockIdx.x * 32 + ty + i * 8;
        int kk = blockIdx.y * 32 + tx;
        float f = t[tx][ty + i * 8];
        __half hi = __float2half_rn(f);
        g_WThi[base + (size_t)nn * DMODEL + kk] = hi;
        g_WTlo[base + (size_t)nn * DMODEL + kk] = __float2half_rn(f - __half2float(hi));
    }
}

// ---------------- mma.sync split-fp16 projection GEMM ----------------------
// Q/K: full 3-term split (hh+hl+lh). V (which==2): hh only.
// 4 warps of 64x64 (CTA 128x128): 32 LDSM : 192 MMA per chunk per warp (1:6).
constexpr int GKC = 32;
constexpr int NCHUNK = DMODEL / GKC;       // 32
constexpr int SST = 40;
constexpr uint32_t AHI = 0;
constexpr uint32_t ALO = 128 * SST * 2;
constexpr uint32_t BHI = 2 * 128 * SST * 2;
constexpr uint32_t BLO = 3 * 128 * SST * 2;
constexpr uint32_t STAGE = 4 * 128 * SST * 2;      // 40960
constexpr uint32_t GEMM_SMEM = 2 * STAGE;          // 81920

__global__ __launch_bounds__(128, 2)
void qkv_mma_kernel()
{
    extern __shared__ uint8_t sm[];
    const uint32_t sb = smem_u32(sm);

    const int tid = threadIdx.x;
    const int lane = tid & 31;
    const int warp = tid >> 5;           // 0..3
    const int wy = warp >> 1;            // 0..1 -> m offset 64*wy
    const int wx = warp & 1;             // 0..1 -> n offset 64*wx
    const int gid = lane >> 2;
    const int tig = lane & 3;

    const int which = blockIdx.z;
    const bool isV = (which == 2);
    const int n0 = blockIdx.x * 128;
    const int m0 = blockIdx.y * 128;

    const __half* __restrict__ WThi = g_WThi + (size_t)which * DMODEL * DMODEL;
    const __half* __restrict__ WTlo = g_WTlo + (size_t)which * DMODEL * DMODEL;

    const uint32_t a_off = ((uint32_t)((lane & 15) * SST) + ((uint32_t)(lane >> 4) << 3)) * 2;
    const uint32_t b_off = ((uint32_t)(((lane & 7) + ((lane >> 4) << 3)) * SST) + (uint32_t)(lane & 8)) * 2;

    auto load_chunk = [&](int c, int s) {
        const uint32_t stage = sb + (uint32_t)s * STAGE;
        const int c0 = c * GKC;
#pragma unroll
        for (int it = 0; it < 4; it++) {
            int idx = tid + it * 128;          // 0..511
            int r = idx >> 2, kg = idx & 3;
            uint32_t doff = (uint32_t)(r * SST * 2 + kg * 16);
            size_t asrc = (size_t)(m0 + r) * DMODEL + c0 + kg * 8;
            size_t bsrc = (size_t)(n0 + r) * DMODEL + c0 + kg * 8;
            cp16(stage + AHI + doff, g_Xhi + asrc);
            cp16(stage + BHI + doff, WThi + bsrc);
            if (!isV) {
                cp16(stage + ALO + doff, g_Xlo + asrc);
                cp16(stage + BLO + doff, WTlo + bsrc);
            }
        }
    };

    float acc[4][8][4];                  // [mt][n8][frag]
#pragma unroll
    for (int mt = 0; mt < 4; mt++)
#pragma unroll
        for (int nt = 0; nt < 8; nt++)
#pragma unroll
            for (int j = 0; j < 4; j++) acc[mt][nt][j] = 0.f;

    load_chunk(0, 0);
    CP_COMMIT();

    for (int c = 0; c < NCHUNK; c++) {
        const int s = c & 1;
        if (c + 1 < NCHUNK) {
            load_chunk(c + 1, s ^ 1);
            CP_COMMIT();
            CP_WAIT(1);
        } else {
            CP_WAIT(0);
        }
        __syncthreads();

        const uint32_t stg = sb + (uint32_t)s * STAGE;

        if (!isV) {
#pragma unroll
            for (int ks = 0; ks < 2; ks++) {
                const uint32_t koff = (uint32_t)(ks * 32);
                uint32_t bh4[4][4], bl4[4][4];
#pragma unroll
                for (int np = 0; np < 4; np++) {
                    const uint32_t brow = (uint32_t)((wx * 64 + np * 16) * SST * 2);
                    ldsm4(bh4[np], stg + BHI + brow + koff + b_off);
                    ldsm4(bl4[np], stg + BLO + brow + koff + b_off);
                }
#pragma unroll
                for (int mt = 0; mt < 4; mt++) {
                    const uint32_t arow = (uint32_t)((wy * 64 + mt * 16) * SST * 2);
                    uint32_t ah[4], al[4];
                    ldsm4(ah, stg + AHI + arow + koff + a_off);
                    ldsm4(al, stg + ALO + arow + koff + a_off);
#pragma unroll
                    for (int np = 0; np < 4; np++) {
                        mma16816(acc[mt][2 * np],     ah, bh4[np]);
                        mma16816(acc[mt][2 * np],     ah, bl4[np]);
                        mma16816(acc[mt][2 * np],     al, bh4[np]);
                        mma16816(acc[mt][2 * np + 1], ah, bh4[np] + 2);
                        mma16816(acc[mt][2 * np + 1], ah, bl4[np] + 2);
                        mma16816(acc[mt][2 * np + 1], al, bh4[np] + 2);
                    }
                }
            }
        } else {
#pragma unroll
            for (int ks = 0; ks < 2; ks++) {
                const uint32_t koff = (uint32_t)(ks * 32);
                uint32_t bh4[4][4];
#pragma unroll
                for (int np = 0; np < 4; np++) {
                    const uint32_t brow = (uint32_t)((wx * 64 + np * 16) * SST * 2);
                    ldsm4(bh4[np], stg + BHI + brow + koff + b_off);
                }
#pragma unroll
                for (int mt = 0; mt < 4; mt++) {
                    const uint32_t arow = (uint32_t)((wy * 64 + mt * 16) * SST * 2);
                    uint32_t ah[4];
                    ldsm4(ah, stg + AHI + arow + koff + a_off);
#pragma unroll
                    for (int np = 0; np < 4; np++) {
                        mma16816(acc[mt][2 * np],     ah, bh4[np]);
                        mma16816(acc[mt][2 * np + 1], ah, bh4[np] + 2);
                    }
                }
            }
        }
        __syncthreads();
    }

    // ---- epilogue: emit fp16 hi(/lo for Q,K), all [bh][s][d] --------------
    const float QSCALE = 0.18033688011112042f;   // 0.125 * log2(e)
#pragma unroll
    for (int mt = 0; mt < 4; mt++) {
#pragma unroll
        for (int hr = 0; hr < 2; hr++) {
            const int m = m0 + wy * 64 + mt * 16 + gid + hr * 8;
            const int bbp = m >> 11;
            const int sIdx = m & 2047;
#pragma unroll
            for (int nt = 0; nt < 8; nt++) {
                const int n = n0 + wx * 64 + nt * 8 + tig * 2;
                const int h = n >> 6, d = n & 63;
                float v0 = acc[mt][nt][hr * 2 + 0];
                float v1 = acc[mt][nt][hr * 2 + 1];
                if (which == 0) { v0 *= QSCALE; v1 *= QSCALE; }
                __half h0 = __float2half_rn(v0), h1 = __float2half_rn(v1);
                __half* hip = (which == 0) ? g_Qhi : (which == 1) ? g_Khi : g_Vhi;
                size_t idx = ((size_t)(bbp * NHEADS + h) * SEQ + sIdx) * DHEAD + d;
                *(__half2*)(hip + idx) = __halves2half2(h0, h1);
                if (!isV) {
                    __half e0 = __float2half_rn(v0 - __half2float(h0));
                    __half e1 = __float2half_rn(v1 - __half2float(h1));
                    __half* lop = (which == 0) ? g_Qlo : g_Klo;
                    *(__half2*)(lop + idx) = __halves2half2(e0, e1);
                }
            }
        }
    }
}

// ---------------------------------------------------------------------------
// Flash attention (unchanged from R15 — best measured): mma.sync + ldmatrix,
// Q/P fragments in registers, V-hi only, 3 CTAs/SM.
// ---------------------------------------------------------------------------
constexpr int AST = 72;                       // smem row stride in halves
constexpr uint32_t QHI_O = 0;
constexpr uint32_t QLO_O = 9216;
constexpr uint32_t STG_O = 18432;
constexpr uint32_t STGSZ = 27648;             // KH/KL/VH x 9216
constexpr uint32_t KH_O = 0, KL_O = 9216, VH_O = 18432;
constexpr uint32_t ATTN_SMEM = STG_O + 2 * STGSZ;   // 73728 -> 3 CTAs/SM

__global__ __launch_bounds__(128, 3)
void attn_mma_kernel(float* __restrict__ out)
{
    extern __shared__ uint8_t sm[];
    const uint32_t sb = smem_u32(sm);

    const int tid = threadIdx.x;
    const int lane = tid & 31;
    const int w = tid >> 5;                        // 0..3
    const int gid = lane >> 2;
    const int tig = lane & 3;
    const int bh = blockIdx.y;
    const int qt = (gridDim.x - 1) - blockIdx.x;   // heavy blocks first
    const int q0 = qt * 64;
    const int bb = bh >> 4, h = bh & 15;

    const uint32_t a_off = ((uint32_t)((lane & 15) * AST) + ((uint32_t)(lane >> 4) << 3)) * 2;
    const uint32_t b_off = ((uint32_t)(((lane & 7) + ((lane >> 4) << 3)) * AST) + (uint32_t)(lane & 8)) * 2;
    const uint32_t v_off = ((uint32_t)(((lane & 7) + ((lane >> 3) & 1) * 8) * AST) + ((uint32_t)(lane >> 4) << 3)) * 2;

    // ---- Q tile load (hi+lo): 64 rows x 64 d -----------------------------
#pragma unroll
    for (int comp = 0; comp < 2; comp++) {
#pragma unroll
        for (int it = 0; it < 4; it++) {
            int idx = tid + it * 128;
            int r = idx >> 3, g = idx & 7;
            uint32_t dst = sb + (comp ? QLO_O : QHI_O) + (uint32_t)(r * 144 + g * 16);
            const __half* src = (comp ? g_Qlo : g_Qhi) +
                                ((size_t)bh * SEQ + q0 + r) * DHEAD + g * 8;
            cp16(dst, src);
        }
    }

    auto load_kv = [&](int kt, int s) {
        uint32_t stage = sb + STG_O + (uint32_t)s * STGSZ;
        const __half* bases[3] = { g_Khi, g_Klo, g_Vhi };
#pragma unroll
        for (int comp = 0; comp < 3; comp++) {
#pragma unroll
            for (int it = 0; it < 4; it++) {
                int idx = tid + it * 128;
                int r = idx >> 3, g = idx & 7;
                uint32_t dst = stage + (uint32_t)comp * 9216u + (uint32_t)(r * 144 + g * 16);
                const __half* src = bases[comp] +
                                    ((size_t)bh * SEQ + kt * 64 + r) * DHEAD + g * 8;
                cp16(dst, src);
            }
        }
    };

    load_kv(0, 0);
    CP_COMMIT();
    CP_WAIT(0);
    __syncthreads();

    // ---- hoist Q fragments to registers (invariant across kt) -------------
    uint32_t qh[4][4], ql[4][4];
    {
        const uint32_t qbase = sb + (uint32_t)(w * 16 * AST) * 2 + a_off;
#pragma unroll
        for (int ks = 0; ks < 4; ks++) {
            ldsm4(qh[ks], qbase + QHI_O + ks * 32);
            ldsm4(ql[ks], qbase + QLO_O + ks * 32);
        }
    }

    float m0 = -1e30f, m1 = -1e30f, l0 = 0.f, l1 = 0.f;
    float oacc[8][4];
#pragma unroll
    for (int nt = 0; nt < 8; nt++)
#pragma unroll
        for (int j = 0; j < 4; j++) oacc[nt][j] = 0.f;

    const int ktmax = min(qt + 1, SEQ / 64 - 1);
    const int rowbase = w * 16 + gid;

    for (int kt = 0; kt <= ktmax; kt++) {
        const int s = kt & 1;
        if (kt) __syncthreads();                  // stage s^1 free for reuse
        if (kt < ktmax) {
            load_kv(kt + 1, s ^ 1);
            CP_COMMIT();
            CP_WAIT(1);
        } else {
            CP_WAIT(0);
        }
        __syncthreads();

        const uint32_t stg = sb + STG_O + (uint32_t)s * STGSZ;

        // ---- S = Q K^T (split fp16, fp32 acc, ldmatrix B) ----------------
        float sacc[8][4];
#pragma unroll
        for (int nt = 0; nt < 8; nt++)
#pragma unroll
            for (int j = 0; j < 4; j++) sacc[nt][j] = 0.f;

#pragma unroll
        for (int ks = 0; ks < 4; ks++) {
            const uint32_t kofs = (uint32_t)(ks * 32) + b_off;
#pragma unroll
            for (int np = 0; np < 4; np++) {
                uint32_t kh4[4], kl4[4];
                ldsm4(kh4, stg + KH_O + (uint32_t)(np * 16 * AST * 2) + kofs);
                ldsm4(kl4, stg + KL_O + (uint32_t)(np * 16 * AST * 2) + kofs);
                mma16816(sacc[2 * np],     qh[ks], kh4);
                mma16816(sacc[2 * np],     qh[ks], kl4);
                mma16816(sacc[2 * np],     ql[ks], kh4);
                mma16816(sacc[2 * np + 1], qh[ks], kh4 + 2);
                mma16816(sacc[2 * np + 1], qh[ks], kl4 + 2);
                mma16816(sacc[2 * np + 1], ql[ks], kh4 + 2);
            }
        }

        // ---- mask: valid iff k <= q+1 (only kt >= qt tiles clip) ---------
        if (kt >= qt) {
            const int qg0 = q0 + rowbase, qg1 = qg0 + 8;
#pragma unroll
            for (int nt = 0; nt < 8; nt++) {
                const int c0 = kt * 64 + nt * 8 + tig * 2;
                if (c0     > qg0 + 1) sacc[nt][0] = -1e30f;
                if (c0 + 1 > qg0 + 1) sacc[nt][1] = -1e30f;
                if (c0     > qg1 + 1) sacc[nt][2] = -1e30f;
                if (c0 + 1 > qg1 + 1) sacc[nt][3] = -1e30f;
            }
        }

        // ---- online softmax, base-2 (MUFU ex2) ---------------------------
        float r0 = -1e30f, r1 = -1e30f;
#pragma unroll
        for (int nt = 0; nt < 8; nt++) {
            r0 = fmaxf(r0, fmaxf(sacc[nt][0], sacc[nt][1]));
            r1 = fmaxf(r1, fmaxf(sacc[nt][2], sacc[nt][3]));
        }
        r0 = fmaxf(r0, __shfl_xor_sync(0xffffffffu, r0, 1));
        r0 = fmaxf(r0, __shfl_xor_sync(0xffffffffu, r0, 2));
        r1 = fmaxf(r1, __shfl_xor_sync(0xffffffffu, r1, 1));
        r1 = fmaxf(r1, __shfl_xor_sync(0xffffffffu, r1, 2));

        const float mn0 = fmaxf(m0, r0), mn1 = fmaxf(m1, r1);
        const float sc0 = fex2(m0 - mn0), sc1 = fex2(m1 - mn1);
        m0 = mn0; m1 = mn1;

        // exp2 + pack P-hi directly into PV A-operand fragments
        uint32_t pha[4][4];
        float rs0 = 0.f, rs1 = 0.f;
#pragma unroll
        for (int nt = 0; nt < 8; nt++) {
            float p0 = fex2(sacc[nt][0] - mn0);
            float p1 = fex2(sacc[nt][1] - mn0);
            float p2 = fex2(sacc[nt][2] - mn1);
            float p3 = fex2(sacc[nt][3] - mn1);
            rs0 += p0 + p1;
            rs1 += p2 + p3;
            const int ks = nt >> 1, hi2 = (nt & 1) << 1;
            pha[ks][hi2 + 0] = pack2h(__float2half_rn(p0), __float2half_rn(p1));  // row g
            pha[ks][hi2 + 1] = pack2h(__float2half_rn(p2), __float2half_rn(p3));  // row g+8
        }

        rs0 += __shfl_xor_sync(0xffffffffu, rs0, 1);
        rs0 += __shfl_xor_sync(0xffffffffu, rs0, 2);
        rs1 += __shfl_xor_sync(0xffffffffu, rs1, 1);
        rs1 += __shfl_xor_sync(0xffffffffu, rs1, 2);
        l0 = l0 * sc0 + rs0;
        l1 = l1 * sc1 + rs1;
#pragma unroll
        for (int nt = 0; nt < 8; nt++) {
            oacc[nt][0] *= sc0; oacc[nt][1] *= sc0;
            oacc[nt][2] *= sc1; oacc[nt][3] *= sc1;
        }

        // ---- O += P V (P-hi x V-hi, trans-ldmatrix V) --------------------
#pragma unroll
        for (int ks = 0; ks < 4; ks++) {
            const uint32_t srow = (uint32_t)(ks * 16 * AST * 2) + v_off;
#pragma unroll
            for (int np = 0; np < 4; np++) {
                uint32_t vh4[4];
                ldsm4t(vh4, stg + VH_O + srow + (uint32_t)(np * 32));
                mma16816(oacc[2 * np],     pha[ks], vh4);
                mma16816(oacc[2 * np + 1], pha[ks], vh4 + 2);
            }
        }
    }

    // ---- epilogue: out[b][s][h*64+d] --------------------------------------
    const float inv0 = 1.f / l0, inv1 = 1.f / l1;
    const int s0 = q0 + rowbase;
#pragma unroll
    for (int nt = 0; nt < 8; nt++) {
        const int d = h * DHEAD + nt * 8 + tig * 2;
        size_t i0 = ((size_t)(bb * SEQ + s0)) * DMODEL + d;
        size_t i1 = ((size_t)(bb * SEQ + s0 + 8)) * DMODEL + d;
        *(float2*)(out + i0) = make_float2(oacc[nt][0] * inv0, oacc[nt][1] * inv0);
        *(float2*)(out + i1) = make_float2(oacc[nt][2] * inv1, oacc[nt][3] * inv1);
    }
}

// ---------------------------------------------------------------------------
extern "C" void kernel_launch(void* const* d_in, const int* in_sizes, int n_in,
                              void* d_out, int out_size)
{
    const float* X  = (const float*)d_in[0];
    const float* Wq = (const float*)d_in[1];
    const float* Wk = (const float*)d_in[2];
    const float* Wv = (const float*)d_in[3];
    float* out = (float*)d_out;

    cudaFuncSetAttribute(qkv_mma_kernel,
                         cudaFuncAttributeMaxDynamicSharedMemorySize, GEMM_SMEM);
    cudaFuncSetAttribute(attn_mma_kernel,
                         cudaFuncAttributeMaxDynamicSharedMemorySize, ATTN_SMEM);

    split_x_kernel<<<(MTOT * DMODEL) / (256 * 4), 256>>>(X);
    split_wt_kernel<<<dim3(32, 32, 3), dim3(32, 8)>>>(Wq, Wk, Wv);

    dim3 ggrid(DMODEL / 128, MTOT / 128, 3);   // 8 x 64 x 3
    qkv_mma_kernel<<<ggrid, 128, GEMM_SMEM>>>();

    dim3 agrid(SEQ / 64, NBH);                 // 32 x 64
    attn_mma_kernel<<<agrid, 128, ATTN_SMEM>>>(out);
}

// round 17
// speedup vs baseline: 1.4069x; 1.0161x over previous
#include <cuda_runtime.h>
#include <cuda_fp16.h>
#include <cstdint>
#include <math.h>

#define BATCH  4
#define SEQ    2048
#define DMODEL 1024
#define NHEADS 16
#define DHEAD  64
#define NBH    (BATCH * NHEADS)   // 64
#define MTOT   (BATCH * SEQ)      // 8192

// ---------------- scratch (static device arrays; allocation-free) ----------
// Q,K,V all [bh][s][d] (d contiguous). Q pre-scaled by 0.125*log2(e).
__device__ __half g_Qhi[(size_t)NBH * SEQ * DHEAD];
__device__ __half g_Qlo[(size_t)NBH * SEQ * DHEAD];
__device__ __half g_Khi[(size_t)NBH * SEQ * DHEAD];
__device__ __half g_Klo[(size_t)NBH * SEQ * DHEAD];
__device__ __half g_Vhi[(size_t)NBH * SEQ * DHEAD];

__device__ __half g_Xhi[(size_t)MTOT * DMODEL];
__device__ __half g_Xlo[(size_t)MTOT * DMODEL];
__device__ __half g_WThi[(size_t)3 * DMODEL * DMODEL];  // [which][n][k]
__device__ __half g_WTlo[(size_t)3 * DMODEL * DMODEL];

// ---------------- helpers ---------------------------------------------------
__device__ __forceinline__ void cp16(uint32_t dst, const void* src) {
    asm volatile("cp.async.cg.shared.global [%0], [%1], 16;" :: "r"(dst), "l"(src));
}
#define CP_COMMIT() asm volatile("cp.async.commit_group;" ::: "memory")
#define CP_WAIT(n)  asm volatile("cp.async.wait_group %0;" :: "n"(n) : "memory")

__device__ __forceinline__ uint32_t smem_u32(const void* p) {
    uint32_t a;
    asm("{ .reg .u64 t; cvta.to.shared.u64 t, %1; cvt.u32.u64 %0, t; }" : "=r"(a) : "l"(p));
    return a;
}
__device__ __forceinline__ void mma16816(float* c, const uint32_t* a, const uint32_t* b) {
    asm volatile("mma.sync.aligned.m16n8k16.row.col.f32.f16.f16.f32 "
                 "{%0,%1,%2,%3}, {%4,%5,%6,%7}, {%8,%9}, {%0,%1,%2,%3};"
                 : "+f"(c[0]), "+f"(c[1]), "+f"(c[2]), "+f"(c[3])
                 : "r"(a[0]), "r"(a[1]), "r"(a[2]), "r"(a[3]), "r"(b[0]), "r"(b[1]));
}
__device__ __forceinline__ void ldsm4(uint32_t* r, uint32_t addr) {
    asm volatile("ldmatrix.sync.aligned.m8n8.x4.shared.b16 {%0,%1,%2,%3}, [%4];"
                 : "=r"(r[0]), "=r"(r[1]), "=r"(r[2]), "=r"(r[3]) : "r"(addr));
}
__device__ __forceinline__ void ldsm4t(uint32_t* r, uint32_t addr) {
    asm volatile("ldmatrix.sync.aligned.m8n8.x4.trans.shared.b16 {%0,%1,%2,%3}, [%4];"
                 : "=r"(r[0]), "=r"(r[1]), "=r"(r[2]), "=r"(r[3]) : "r"(addr));
}
// pack two floats to fp16x2 in ONE cvt (lo = first arg)
__device__ __forceinline__ uint32_t packf2(float lo, float hi) {
    uint32_t r;
    asm("cvt.rn.f16x2.f32 %0, %1, %2;" : "=r"(r) : "f"(hi), "f"(lo));
    return r;
}
// MUFU exp2 (logits are pre-scaled to base-2 domain)
__device__ __forceinline__ float fex2(float x) {
    float r;
    asm("ex2.approx.f32 %0, %1;" : "=f"(r) : "f"(x));
    return r;
}

// ---------------- conversion kernels ---------------------------------------
__global__ void split_x_kernel(const float* __restrict__ X)
{
    size_t i = ((size_t)blockIdx.x * blockDim.x + threadIdx.x) * 4;
    float4 v = *(const float4*)(X + i);
    float f[4] = {v.x, v.y, v.z, v.w};
#pragma unroll
    for (int j = 0; j < 4; j++) {
        __half hi = __float2half_rn(f[j]);
        g_Xhi[i + j] = hi;
        g_Xlo[i + j] = __float2half_rn(f[j] - __half2float(hi));
    }
}

__global__ void split_wt_kernel(const float* __restrict__ Wq,
                                const float* __restrict__ Wk,
                                const float* __restrict__ Wv)
{
    __shared__ float t[32][33];
    const float* W = (blockIdx.z == 0) ? Wq : (blockIdx.z == 1) ? Wk : Wv;
    int tx = threadIdx.x, ty = threadIdx.y;
    int n = blockIdx.x * 32 + tx;
#pragma unroll
    for (int i = 0; i < 4; i++) {
        int k = blockIdx.y * 32 + ty + i * 8;
        t[ty + i * 8][tx] = W[(size_t)k * DMODEL + n];
    }
    __syncthreads();
    size_t base = (size_t)blockIdx.z * DMODEL * DMODEL;
#pragma unroll
    for (int i = 0; i < 4; i++) {
        int nn = blockIdx.x * 32 + ty + i * 8;
        int kk = blockIdx.y * 32 + tx;
        float f = t[tx][ty + i * 8];
        __half hi = __float2half_rn(f);
        g_WThi[base + (size_t)nn * DMODEL + kk] = hi;
        g_WTlo[base + (size_t)nn * DMODEL + kk] = __float2half_rn(f - __half2float(hi));
    }
}

// ---------------- mma.sync split-fp16 projection GEMM ----------------------
// Q/K: full 3-term split (hh+hl+lh). V (which==2): hh only.
// 4 warps of 64x64 (CTA 128x128): 32 LDSM : 192 MMA per chunk per warp (1:6).
constexpr int GKC = 32;
constexpr int NCHUNK = DMODEL / GKC;       // 32
constexpr int SST = 40;
constexpr uint32_t AHI = 0;
constexpr uint32_t ALO = 128 * SST * 2;
constexpr uint32_t BHI = 2 * 128 * SST * 2;
constexpr uint32_t BLO = 3 * 128 * SST * 2;
constexpr uint32_t STAGE = 4 * 128 * SST * 2;      // 40960
constexpr uint32_t GEMM_SMEM = 2 * STAGE;          // 81920

__global__ __launch_bounds__(128, 2)
void qkv_mma_kernel()
{
    extern __shared__ uint8_t sm[];
    const uint32_t sb = smem_u32(sm);

    const int tid = threadIdx.x;
    const int lane = tid & 31;
    const int warp = tid >> 5;           // 0..3
    const int wy = warp >> 1;            // 0..1 -> m offset 64*wy
    const int wx = warp & 1;             // 0..1 -> n offset 64*wx
    const int gid = lane >> 2;
    const int tig = lane & 3;

    const int which = blockIdx.z;
    const bool isV = (which == 2);
    const int n0 = blockIdx.x * 128;
    const int m0 = blockIdx.y * 128;

    const __half* __restrict__ WThi = g_WThi + (size_t)which * DMODEL * DMODEL;
    const __half* __restrict__ WTlo = g_WTlo + (size_t)which * DMODEL * DMODEL;

    const uint32_t a_off = ((uint32_t)((lane & 15) * SST) + ((uint32_t)(lane >> 4) << 3)) * 2;
    const uint32_t b_off = ((uint32_t)(((lane & 7) + ((lane >> 4) << 3)) * SST) + (uint32_t)(lane & 8)) * 2;

    auto load_chunk = [&](int c, int s) {
        const uint32_t stage = sb + (uint32_t)s * STAGE;
        const int c0 = c * GKC;
#pragma unroll
        for (int it = 0; it < 4; it++) {
            int idx = tid + it * 128;          // 0..511
            int r = idx >> 2, kg = idx & 3;
            uint32_t doff = (uint32_t)(r * SST * 2 + kg * 16);
            size_t asrc = (size_t)(m0 + r) * DMODEL + c0 + kg * 8;
            size_t bsrc = (size_t)(n0 + r) * DMODEL + c0 + kg * 8;
            cp16(stage + AHI + doff, g_Xhi + asrc);
            cp16(stage + BHI + doff, WThi + bsrc);
            if (!isV) {
                cp16(stage + ALO + doff, g_Xlo + asrc);
                cp16(stage + BLO + doff, WTlo + bsrc);
            }
        }
    };

    float acc[4][8][4];                  // [mt][n8][frag]
#pragma unroll
    for (int mt = 0; mt < 4; mt++)
#pragma unroll
        for (int nt = 0; nt < 8; nt++)
#pragma unroll
            for (int j = 0; j < 4; j++) acc[mt][nt][j] = 0.f;

    load_chunk(0, 0);
    CP_COMMIT();

    for (int c = 0; c < NCHUNK; c++) {
        const int s = c & 1;
        if (c + 1 < NCHUNK) {
            load_chunk(c + 1, s ^ 1);
            CP_COMMIT();
            CP_WAIT(1);
        } else {
            CP_WAIT(0);
        }
        __syncthreads();

        const uint32_t stg = sb + (uint32_t)s * STAGE;

        if (!isV) {
#pragma unroll
            for (int ks = 0; ks < 2; ks++) {
                const uint32_t koff = (uint32_t)(ks * 32);
                uint32_t bh4[4][4], bl4[4][4];
#pragma unroll
                for (int np = 0; np < 4; np++) {
                    const uint32_t brow = (uint32_t)((wx * 64 + np * 16) * SST * 2);
                    ldsm4(bh4[np], stg + BHI + brow + koff + b_off);
                    ldsm4(bl4[np], stg + BLO + brow + koff + b_off);
                }
#pragma unroll
                for (int mt = 0; mt < 4; mt++) {
                    const uint32_t arow = (uint32_t)((wy * 64 + mt * 16) * SST * 2);
                    uint32_t ah[4], al[4];
                    ldsm4(ah, stg + AHI + arow + koff + a_off);
                    ldsm4(al, stg + ALO + arow + koff + a_off);
#pragma unroll
                    for (int np = 0; np < 4; np++) {
                        mma16816(acc[mt][2 * np],     ah, bh4[np]);
                        mma16816(acc[mt][2 * np],     ah, bl4[np]);
                        mma16816(acc[mt][2 * np],     al, bh4[np]);
                        mma16816(acc[mt][2 * np + 1], ah, bh4[np] + 2);
                        mma16816(acc[mt][2 * np + 1], ah, bl4[np] + 2);
                        mma16816(acc[mt][2 * np + 1], al, bh4[np] + 2);
                    }
                }
            }
        } else {
#pragma unroll
            for (int ks = 0; ks < 2; ks++) {
                const uint32_t koff = (uint32_t)(ks * 32);
                uint32_t bh4[4][4];
#pragma unroll
                for (int np = 0; np < 4; np++) {
                    const uint32_t brow = (uint32_t)((wx * 64 + np * 16) * SST * 2);
                    ldsm4(bh4[np], stg + BHI + brow + koff + b_off);
                }
#pragma unroll
                for (int mt = 0; mt < 4; mt++) {
                    const uint32_t arow = (uint32_t)((wy * 64 + mt * 16) * SST * 2);
                    uint32_t ah[4];
                    ldsm4(ah, stg + AHI + arow + koff + a_off);
#pragma unroll
                    for (int np = 0; np < 4; np++) {
                        mma16816(acc[mt][2 * np],     ah, bh4[np]);
                        mma16816(acc[mt][2 * np + 1], ah, bh4[np] + 2);
                    }
                }
            }
        }
        __syncthreads();
    }

    // ---- epilogue: emit fp16 hi(/lo for Q,K), all [bh][s][d] --------------
    const float QSCALE = 0.18033688011112042f;   // 0.125 * log2(e)
#pragma unroll
    for (int mt = 0; mt < 4; mt++) {
#pragma unroll
        for (int hr = 0; hr < 2; hr++) {
            const int m = m0 + wy * 64 + mt * 16 + gid + hr * 8;
            const int bbp = m >> 11;
            const int sIdx = m & 2047;
#pragma unroll
            for (int nt = 0; nt < 8; nt++) {
                const int n = n0 + wx * 64 + nt * 8 + tig * 2;
                const int h = n >> 6, d = n & 63;
                float v0 = acc[mt][nt][hr * 2 + 0];
                float v1 = acc[mt][nt][hr * 2 + 1];
                if (which == 0) { v0 *= QSCALE; v1 *= QSCALE; }
                __half h0 = __float2half_rn(v0), h1 = __float2half_rn(v1);
                __half* hip = (which == 0) ? g_Qhi : (which == 1) ? g_Khi : g_Vhi;
                size_t idx = ((size_t)(bbp * NHEADS + h) * SEQ + sIdx) * DHEAD + d;
                *(__half2*)(hip + idx) = __halves2half2(h0, h1);
                if (!isV) {
                    __half e0 = __float2half_rn(v0 - __half2float(h0));
                    __half e1 = __float2half_rn(v1 - __half2float(h1));
                    __half* lop = (which == 0) ? g_Qlo : g_Klo;
                    *(__half2*)(lop + idx) = __halves2half2(e0, e1);
                }
            }
        }
    }
}

// ---------------------------------------------------------------------------
// Flash attention: mma.sync + ldmatrix, Q/P fragments in registers, V-hi only,
// 3 CTAs/SM. Main loop runs kt<=qt; the diagonal+1 tile (exactly ONE valid
// element: row 63, key 64qt+64) is handled by a scalar correction.
// ---------------------------------------------------------------------------
constexpr int AST = 72;                       // smem row stride in halves
constexpr uint32_t QHI_O = 0;
constexpr uint32_t QLO_O = 9216;
constexpr uint32_t STG_O = 18432;
constexpr uint32_t STGSZ = 27648;             // KH/KL/VH x 9216
constexpr uint32_t KH_O = 0, KL_O = 9216, VH_O = 18432;
constexpr uint32_t ATTN_SMEM = STG_O + 2 * STGSZ;   // 73728 -> 3 CTAs/SM

__global__ __launch_bounds__(128, 3)
void attn_mma_kernel(float* __restrict__ out)
{
    extern __shared__ uint8_t sm[];
    const uint32_t sb = smem_u32(sm);

    const int tid = threadIdx.x;
    const int lane = tid & 31;
    const int w = tid >> 5;                        // 0..3
    const int gid = lane >> 2;
    const int tig = lane & 3;
    const int bh = blockIdx.y;
    const int qt = (gridDim.x - 1) - blockIdx.x;   // heavy blocks first
    const int q0 = qt * 64;
    const int bb = bh >> 4, h = bh & 15;

    const uint32_t a_off = ((uint32_t)((lane & 15) * AST) + ((uint32_t)(lane >> 4) << 3)) * 2;
    const uint32_t b_off = ((uint32_t)(((lane & 7) + ((lane >> 4) << 3)) * AST) + (uint32_t)(lane & 8)) * 2;
    const uint32_t v_off = ((uint32_t)(((lane & 7) + ((lane >> 3) & 1) * 8) * AST) + ((uint32_t)(lane >> 4) << 3)) * 2;

    // ---- Q tile load (hi+lo): 64 rows x 64 d -----------------------------
#pragma unroll
    for (int comp = 0; comp < 2; comp++) {
#pragma unroll
        for (int it = 0; it < 4; it++) {
            int idx = tid + it * 128;
            int r = idx >> 3, g = idx & 7;
            uint32_t dst = sb + (comp ? QLO_O : QHI_O) + (uint32_t)(r * 144 + g * 16);
            const __half* src = (comp ? g_Qlo : g_Qhi) +
                                ((size_t)bh * SEQ + q0 + r) * DHEAD + g * 8;
            cp16(dst, src);
        }
    }

    auto load_kv = [&](int kt, int s) {
        uint32_t stage = sb + STG_O + (uint32_t)s * STGSZ;
        const __half* bases[3] = { g_Khi, g_Klo, g_Vhi };
#pragma unroll
        for (int comp = 0; comp < 3; comp++) {
#pragma unroll
            for (int it = 0; it < 4; it++) {
                int idx = tid + it * 128;
                int r = idx >> 3, g = idx & 7;
                uint32_t dst = stage + (uint32_t)comp * 9216u + (uint32_t)(r * 144 + g * 16);
                const __half* src = bases[comp] +
                                    ((size_t)bh * SEQ + kt * 64 + r) * DHEAD + g * 8;
                cp16(dst, src);
            }
        }
    };

    load_kv(0, 0);
    CP_COMMIT();
    CP_WAIT(0);
    __syncthreads();

    // ---- hoist Q fragments to registers (invariant across kt) -------------
    uint32_t qh[4][4], ql[4][4];
    {
        const uint32_t qbase = sb + (uint32_t)(w * 16 * AST) * 2 + a_off;
#pragma unroll
        for (int ks = 0; ks < 4; ks++) {
            ldsm4(qh[ks], qbase + QHI_O + ks * 32);
            ldsm4(ql[ks], qbase + QLO_O + ks * 32);
        }
    }

    float m0 = -1e30f, m1 = -1e30f, l0 = 0.f, l1 = 0.f;
    float oacc[8][4];
#pragma unroll
    for (int nt = 0; nt < 8; nt++)
#pragma unroll
        for (int j = 0; j < 4; j++) oacc[nt][j] = 0.f;

    const int ktmax = qt;                 // diag+1 tile replaced by correction
    const int rowbase = w * 16 + gid;

    for (int kt = 0; kt <= ktmax; kt++) {
        const int s = kt & 1;
        if (kt) __syncthreads();                  // stage s^1 free for reuse
        if (kt < ktmax) {
            load_kv(kt + 1, s ^ 1);
            CP_COMMIT();
            CP_WAIT(1);
        } else {
            CP_WAIT(0);
        }
        __syncthreads();

        const uint32_t stg = sb + STG_O + (uint32_t)s * STGSZ;

        // ---- S = Q K^T (split fp16, fp32 acc, ldmatrix B) ----------------
        float sacc[8][4];
#pragma unroll
        for (int nt = 0; nt < 8; nt++)
#pragma unroll
            for (int j = 0; j < 4; j++) sacc[nt][j] = 0.f;

#pragma unroll
        for (int ks = 0; ks < 4; ks++) {
            const uint32_t kofs = (uint32_t)(ks * 32) + b_off;
#pragma unroll
            for (int np = 0; np < 4; np++) {
                uint32_t kh4[4], kl4[4];
                ldsm4(kh4, stg + KH_O + (uint32_t)(np * 16 * AST * 2) + kofs);
                ldsm4(kl4, stg + KL_O + (uint32_t)(np * 16 * AST * 2) + kofs);
                mma16816(sacc[2 * np],     qh[ks], kh4);
                mma16816(sacc[2 * np],     qh[ks], kl4);
                mma16816(sacc[2 * np],     ql[ks], kh4);
                mma16816(sacc[2 * np + 1], qh[ks], kh4 + 2);
                mma16816(sacc[2 * np + 1], qh[ks], kl4 + 2);
                mma16816(sacc[2 * np + 1], ql[ks], kh4 + 2);
            }
        }

        // ---- mask (diagonal tile only): valid iff k <= q+1 ---------------
        if (kt == qt) {
            const int qg0 = q0 + rowbase, qg1 = qg0 + 8;
#pragma unroll
            for (int nt = 0; nt < 8; nt++) {
                const int c0 = kt * 64 + nt * 8 + tig * 2;
                if (c0     > qg0 + 1) sacc[nt][0] = -1e30f;
                if (c0 + 1 > qg0 + 1) sacc[nt][1] = -1e30f;
                if (c0     > qg1 + 1) sacc[nt][2] = -1e30f;
                if (c0 + 1 > qg1 + 1) sacc[nt][3] = -1e30f;
            }
        }

        // ---- online softmax, base-2 (MUFU ex2) ---------------------------
        float r0 = -1e30f, r1 = -1e30f;
#pragma unroll
        for (int nt = 0; nt < 8; nt++) {
            r0 = fmaxf(r0, fmaxf(sacc[nt][0], sacc[nt][1]));
            r1 = fmaxf(r1, fmaxf(sacc[nt][2], sacc[nt][3]));
        }
        r0 = fmaxf(r0, __shfl_xor_sync(0xffffffffu, r0, 1));
        r0 = fmaxf(r0, __shfl_xor_sync(0xffffffffu, r0, 2));
        r1 = fmaxf(r1, __shfl_xor_sync(0xffffffffu, r1, 1));
        r1 = fmaxf(r1, __shfl_xor_sync(0xffffffffu, r1, 2));

        const float mn0 = fmaxf(m0, r0), mn1 = fmaxf(m1, r1);
        const float sc0 = fex2(m0 - mn0), sc1 = fex2(m1 - mn1);
        m0 = mn0; m1 = mn1;

        // exp2 + pack P-hi directly into PV A-operand fragments
        uint32_t pha[4][4];
        float rs0 = 0.f, rs1 = 0.f;
#pragma unroll
        for (int nt = 0; nt < 8; nt++) {
            float p0 = fex2(sacc[nt][0] - mn0);
            float p1 = fex2(sacc[nt][1] - mn0);
            float p2 = fex2(sacc[nt][2] - mn1);
            float p3 = fex2(sacc[nt][3] - mn1);
            rs0 += p0 + p1;
            rs1 += p2 + p3;
            const int ks = nt >> 1, hi2 = (nt & 1) << 1;
            pha[ks][hi2 + 0] = packf2(p0, p1);            // row g
            pha[ks][hi2 + 1] = packf2(p2, p3);            // row g+8
        }

        rs0 += __shfl_xor_sync(0xffffffffu, rs0, 1);
        rs0 += __shfl_xor_sync(0xffffffffu, rs0, 2);
        rs1 += __shfl_xor_sync(0xffffffffu, rs1, 1);
        rs1 += __shfl_xor_sync(0xffffffffu, rs1, 2);
        l0 = l0 * sc0 + rs0;
        l1 = l1 * sc1 + rs1;
#pragma unroll
        for (int nt = 0; nt < 8; nt++) {
            oacc[nt][0] *= sc0; oacc[nt][1] *= sc0;
            oacc[nt][2] *= sc1; oacc[nt][3] *= sc1;
        }

        // ---- O += P V (P-hi x V-hi, trans-ldmatrix V) --------------------
#pragma unroll
        for (int ks = 0; ks < 4; ks++) {
            const uint32_t srow = (uint32_t)(ks * 16 * AST * 2) + v_off;
#pragma unroll
            for (int np = 0; np < 4; np++) {
                uint32_t vh4[4];
                ldsm4t(vh4, stg + VH_O + srow + (uint32_t)(np * 32));
                mma16816(oacc[2 * np],     pha[ks], vh4);
                mma16816(oacc[2 * np + 1], pha[ks], vh4 + 2);
            }
        }
    }

    // ---- diag+1 correction: single element (row 63, key q0+64) ------------
    // tril(...,k=1) lets q = q0+63 see key q0+64. Only warp 3 / gid 7 owns
    // row 63 (r1 side). Computed fp32 from gmem; online-update m1/l1/oacc.
    if (qt < SEQ / 64 - 1 && w == 3) {
        const int kk = q0 + 64;
        const size_t qrow = ((size_t)bh * SEQ + q0 + 63) * DHEAD;
        const size_t krow = ((size_t)bh * SEQ + kk) * DHEAD;
        float dot = 0.f;
#pragma unroll
        for (int d = 0; d < 16; d += 2) {
            const int dd = tig * 16 + d;
            __half2 qh2 = *(const __half2*)(g_Qhi + qrow + dd);
            __half2 ql2 = *(const __half2*)(g_Qlo + qrow + dd);
            __half2 kh2 = *(const __half2*)(g_Khi + krow + dd);
            __half2 kl2 = *(const __half2*)(g_Klo + krow + dd);
            float qx = __half2float(__low2half(qh2))  + __half2float(__low2half(ql2));
            float qy = __half2float(__high2half(qh2)) + __half2float(__high2half(ql2));
            float kx = __half2float(__low2half(kh2))  + __half2float(__low2half(kl2));
            float ky = __half2float(__high2half(kh2)) + __half2float(__high2half(kl2));
            dot = fmaf(qx, kx, dot);
            dot = fmaf(qy, ky, dot);
        }
        dot += __shfl_xor_sync(0xffffffffu, dot, 1);   // quad reduce (lanes tig)
        dot += __shfl_xor_sync(0xffffffffu, dot, 2);
        if (gid == 7) {
            const float mn = fmaxf(m1, dot);
            const float sc = fex2(m1 - mn);
            const float p  = fex2(dot - mn);
            m1 = mn;
            l1 = l1 * sc + p;
#pragma unroll
            for (int nt = 0; nt < 8; nt++) {
                float v0 = __half2float(g_Vhi[krow + nt * 8 + tig * 2]);
                float v1 = __half2float(g_Vhi[krow + nt * 8 + tig * 2 + 1]);
                oacc[nt][2] = fmaf(p, v0, oacc[nt][2] * sc);
                oacc[nt][3] = fmaf(p, v1, oacc[nt][3] * sc);
            }
        }
    }

    // ---- epilogue: out[b][s][h*64+d] --------------------------------------
    const float inv0 = 1.f / l0, inv1 = 1.f / l1;
    const int s0 = q0 + rowbase;
#pragma unroll
    for (int nt = 0; nt < 8; nt++) {
        const int d = h * DHEAD + nt * 8 + tig * 2;
        size_t i0 = ((size_t)(bb * SEQ + s0)) * DMODEL + d;
        size_t i1 = ((size_t)(bb * SEQ + s0 + 8)) * DMODEL + d;
        *(float2*)(out + i0) = make_float2(oacc[nt][0] * inv0, oacc[nt][1] * inv0);
        *(float2*)(out + i1) = make_float2(oacc[nt][2] * inv1, oacc[nt][3] * inv1);
    }
}

// ---------------------------------------------------------------------------
extern "C" void kernel_launch(void* const* d_in, const int* in_sizes, int n_in,
                              void* d_out, int out_size)
{
    const float* X  = (const float*)d_in[0];
    const float* Wq = (const float*)d_in[1];
    const float* Wk = (const float*)d_in[2];
    const float* Wv = (const float*)d_in[3];
    float* out = (float*)d_out;

    cudaFuncSetAttribute(qkv_mma_kernel,
                         cudaFuncAttributeMaxDynamicSharedMemorySize, GEMM_SMEM);
    cudaFuncSetAttribute(attn_mma_kernel,
                         cudaFuncAttributeMaxDynamicSharedMemorySize, ATTN_SMEM);

    split_x_kernel<<<(MTOT * DMODEL) / (256 * 4), 256>>>(X);
    split_wt_kernel<<<dim3(32, 32, 3), dim3(32, 8)>>>(Wq, Wk, Wv);

    dim3 ggrid(DMODEL / 128, MTOT / 128, 3);   // 8 x 64 x 3
    qkv_mma_kernel<<<ggrid, 128, GEMM_SMEM>>>();

    dim3 agrid(SEQ / 64, NBH);                 // 32 x 64
    attn_mma_kernel<<<agrid, 128, ATTN_SMEM>>>(out);
}